// round 1
// baseline (speedup 1.0000x reference)
#include <cuda_runtime.h>
#include <cstdint>

// ---------------------------------------------------------------------------
// SoftPatternClassifier on GB300
// Pipeline:
//   1. pack_kernel:  Ap[k][c] = diags[row(c)][k]  (c = p*5+m, m<5; k-major, coalesced)
//   2. gemm_kernel:  table[v][c] = logsig( sum_k Ap[k][c]*E[k][v] + bias[row(c)] )
//   3. scan_kernel:  per-batch Viterbi-style max-sum over L=512 steps + fused
//                    exp/layernorm/heaviside/linear epilogue
// ---------------------------------------------------------------------------

#define BDIM   64
#define LDIM   512
#define VDIM   20000
#define PDIM   150
#define MDIM   6
#define CDIM   750           // P * (M-1) used transition columns
#define KDIM   300
#define NEGF   (-1000000000.0f)

#define CSTR   768           // padded c-stride for Ap
#define TSTR   752           // padded c-stride for table (16B-aligned rows)

// scratch (allocation-free rule: __device__ globals)
__device__ float d_Ap[KDIM * CSTR];          // ~0.9 MB
__device__ float d_table[(size_t)VDIM * TSTR]; // ~60 MB

__device__ __forceinline__ float logsig(float x) {
    // matches jax.nn.log_sigmoid: min(x,0) - log1p(exp(-|x|))
    return fminf(x, 0.0f) - log1pf(expf(-fabsf(x)));
}

// ---------------------------------------------------------------------------
// 1. pack: transpose used diags rows into k-major Ap, zero-pad c in [750,768)
// ---------------------------------------------------------------------------
__global__ void pack_kernel(const float* __restrict__ diags) {
    int i = blockIdx.x * blockDim.x + threadIdx.x;
    if (i >= KDIM * CSTR) return;
    int k = i / CSTR;
    int c = i - k * CSTR;
    float v = 0.0f;
    if (c < CDIM) {
        int p = c / 5;
        int m = c - p * 5;
        v = diags[(p * 6 + m) * KDIM + k];
    }
    d_Ap[i] = v;
}

// ---------------------------------------------------------------------------
// 2. GEMM: tile 128 c  x  64 v, K-tile 20, 256 threads.
//    thread (tx=tid&31 -> 4 contiguous c, ty=tid>>5 -> 8 v)
// ---------------------------------------------------------------------------
#define GBM 128   // c per block
#define GBN 64    // v per block
#define GBK 20

__global__ __launch_bounds__(256, 4)
void gemm_kernel(const float* __restrict__ E,      // [300][20000]
                 const float* __restrict__ bias)   // [900]
{
    __shared__ float sA[GBK][GBM];
    __shared__ float sE[GBK][GBN];

    const int tid   = threadIdx.x;
    const int tx    = tid & 31;   // c-groups of 4
    const int ty    = tid >> 5;   // v-groups of 8
    const int vBase = blockIdx.x * GBN;
    const int cBase = blockIdx.y * GBM;

    float acc[8][4];
#pragma unroll
    for (int j = 0; j < 8; j++)
#pragma unroll
        for (int i = 0; i < 4; i++) acc[j][i] = 0.0f;

    for (int kt = 0; kt < KDIM / GBK; kt++) {
        const int k0 = kt * GBK;
        __syncthreads();
        // load A tile: 20x128 = 2560 elems, 10 per thread, coalesced in c
#pragma unroll
        for (int r = 0; r < 10; r++) {
            int idx = tid + r * 256;
            int k = idx >> 7;
            int c = idx & 127;
            sA[k][c] = d_Ap[(k0 + k) * CSTR + cBase + c];
        }
        // load E tile: 20x64 = 1280 elems, 5 per thread, coalesced in v
#pragma unroll
        for (int r = 0; r < 5; r++) {
            int idx = tid + r * 256;
            int k = idx >> 6;
            int v = idx & 63;
            int gv = vBase + v;
            sE[k][v] = (gv < VDIM) ? E[(k0 + k) * VDIM + gv] : 0.0f;
        }
        __syncthreads();

#pragma unroll
        for (int kk = 0; kk < GBK; kk++) {
            float4 a  = *reinterpret_cast<const float4*>(&sA[kk][tx * 4]);
            float4 b0 = *reinterpret_cast<const float4*>(&sE[kk][ty * 8]);
            float4 b1 = *reinterpret_cast<const float4*>(&sE[kk][ty * 8 + 4]);
            float av[4] = {a.x, a.y, a.z, a.w};
            float bv[8] = {b0.x, b0.y, b0.z, b0.w, b1.x, b1.y, b1.z, b1.w};
#pragma unroll
            for (int j = 0; j < 8; j++)
#pragma unroll
                for (int i = 0; i < 4; i++)
                    acc[j][i] = fmaf(bv[j], av[i], acc[j][i]);
        }
    }

    // epilogue: +bias, log_sigmoid, store table[v][c]
    const int c0 = cBase + tx * 4;
    float bv[4];
#pragma unroll
    for (int i = 0; i < 4; i++) {
        int c = c0 + i;
        if (c < CDIM) {
            int p = c / 5;
            int m = c - p * 5;
            bv[i] = __ldg(&bias[p * 6 + m]);
        } else bv[i] = 0.0f;
    }
    const bool full4 = (c0 + 3) < CDIM;
#pragma unroll
    for (int j = 0; j < 8; j++) {
        int v = vBase + ty * 8 + j;
        if (v >= VDIM) continue;
        float o[4];
#pragma unroll
        for (int i = 0; i < 4; i++) o[i] = logsig(acc[j][i] + bv[i]);
        float* dst = &d_table[(size_t)v * TSTR + c0];
        if (full4) {
            *reinterpret_cast<float4*>(dst) = make_float4(o[0], o[1], o[2], o[3]);
        } else {
#pragma unroll
            for (int i = 0; i < 4; i++)
                if (c0 + i < CDIM) dst[i] = o[i];
        }
    }
}

// ---------------------------------------------------------------------------
// 3. scan: 64 blocks (one per batch), 160 threads (thread = pattern),
//    8-deep register prefetch of the token transition rows, fused epilogue.
// ---------------------------------------------------------------------------
#define PF 8

__global__ __launch_bounds__(160)
void scan_kernel(const int*   __restrict__ docs,
                 const int*   __restrict__ doc_lens,
                 const float* __restrict__ wildcards, // [150][5]
                 const float* __restrict__ gamma,
                 const float* __restrict__ beta,
                 const float* __restrict__ W,         // [2][150]
                 const float* __restrict__ lb,        // [2]
                 float*       __restrict__ out)       // [64][2]
{
    const int b   = blockIdx.x;
    const int tid = threadIdx.x;
    const int p   = tid;
    const bool valid = (p < PDIM);

    __shared__ int   s_tok[LDIM];
    __shared__ float sh[192];
    __shared__ float sred[2];

    for (int i = tid; i < LDIM; i += 160) s_tok[i] = docs[b * LDIM + i];
    __syncthreads();

    float wl[5];
#pragma unroll
    for (int m = 0; m < 5; m++)
        wl[m] = valid ? logsig(__ldg(&wildcards[p * 5 + m])) : 0.0f;

    const int len    = doc_lens[b];
    const int endSel = p / 50;   // 0 -> h3, 1 -> h4, 2 -> h5

    float h1 = NEGF, h2 = NEGF, h3 = NEGF, h4 = NEGF, h5 = NEGF;
    float sc = NEGF;

    float pf[PF][5];
#pragma unroll
    for (int u = 0; u < PF; u++) {
        if (valid) {
            const float* row = &d_table[(size_t)s_tok[u] * TSTR + p * 5];
#pragma unroll
            for (int m = 0; m < 5; m++) pf[u][m] = __ldg(&row[m]);
        } else {
#pragma unroll
            for (int m = 0; m < 5; m++) pf[u][m] = 0.0f;
        }
    }

    for (int t = 0; t < LDIM; t += PF) {
#pragma unroll
        for (int u = 0; u < PF; u++) {
            float e0 = fmaxf(pf[u][0], wl[0]);
            float e1 = fmaxf(pf[u][1], wl[1]);
            float e2 = fmaxf(pf[u][2], wl[2]);
            float e3 = fmaxf(pf[u][3], wl[3]);
            float e4 = fmaxf(pf[u][4], wl[4]);
            h5 = h4 + e4;
            h4 = h3 + e3;
            h3 = h2 + e2;
            h2 = h1 + e1;
            h1 = e0;
            float ev = (endSel == 0) ? h3 : ((endSel == 1) ? h4 : h5);
            int tt = t + u;
            sc = (tt < len) ? fmaxf(sc, ev) : sc;
            int nt = tt + PF;
            if (nt < LDIM && valid) {
                const float* row = &d_table[(size_t)s_tok[nt] * TSTR + p * 5];
#pragma unroll
                for (int m = 0; m < 5; m++) pf[u][m] = __ldg(&row[m]);
            }
        }
    }

    // ---- fused epilogue: exp -> layernorm over P -> heaviside -> linear ----
    float score = valid ? expf(sc) : 0.0f;

    sh[tid] = score;
    __syncthreads();
    if (tid < 32) {
        float s = 0.0f;
        for (int i = tid; i < PDIM; i += 32) s += sh[i];
#pragma unroll
        for (int o = 16; o > 0; o >>= 1) s += __shfl_down_sync(0xffffffffu, s, o);
        if (tid == 0) sred[0] = s * (1.0f / PDIM);
    }
    __syncthreads();
    const float mu = sred[0];

    float d = score - mu;
    sh[tid] = valid ? d * d : 0.0f;
    __syncthreads();
    if (tid < 32) {
        float s = 0.0f;
        for (int i = tid; i < PDIM; i += 32) s += sh[i];
#pragma unroll
        for (int o = 16; o > 0; o >>= 1) s += __shfl_down_sync(0xffffffffu, s, o);
        if (tid == 0) sred[1] = s * (1.0f / PDIM);
    }
    __syncthreads();
    const float var = sred[1];

    float bin = 0.0f;
    if (valid) {
        float norm = (score - mu) * rsqrtf(var + 1e-5f) * __ldg(&gamma[p]) + __ldg(&beta[p]);
        bin = (norm > 0.0f) ? 1.0f : 0.0f;
    }

    sh[tid] = valid ? bin * __ldg(&W[p]) : 0.0f;
    __syncthreads();
    if (tid < 32) {
        float s = 0.0f;
        for (int i = tid; i < PDIM; i += 32) s += sh[i];
#pragma unroll
        for (int o = 16; o > 0; o >>= 1) s += __shfl_down_sync(0xffffffffu, s, o);
        if (tid == 0) out[b * 2 + 0] = s + __ldg(&lb[0]);
    }
    __syncthreads();
    sh[tid] = valid ? bin * __ldg(&W[PDIM + p]) : 0.0f;
    __syncthreads();
    if (tid < 32) {
        float s = 0.0f;
        for (int i = tid; i < PDIM; i += 32) s += sh[i];
#pragma unroll
        for (int o = 16; o > 0; o >>= 1) s += __shfl_down_sync(0xffffffffu, s, o);
        if (tid == 0) out[b * 2 + 1] = s + __ldg(&lb[1]);
    }
}

// ---------------------------------------------------------------------------
// launch
// ---------------------------------------------------------------------------
extern "C" void kernel_launch(void* const* d_in, const int* in_sizes, int n_in,
                              void* d_out, int out_size)
{
    const int*   docs      = (const int*)  d_in[0];
    const int*   doc_lens  = (const int*)  d_in[1];
    const float* emb       = (const float*)d_in[2];
    const float* diags     = (const float*)d_in[3];
    const float* bias      = (const float*)d_in[4];
    const float* wildcards = (const float*)d_in[5];
    const float* ln_gamma  = (const float*)d_in[6];
    const float* ln_beta   = (const float*)d_in[7];
    const float* linear_w  = (const float*)d_in[8];
    const float* linear_b  = (const float*)d_in[9];
    float*       out       = (float*)d_out;

    (void)in_sizes; (void)n_in; (void)out_size;

    // 1. pack diags
    pack_kernel<<<(KDIM * CSTR + 255) / 256, 256>>>(diags);

    // 2. GEMM + logsig -> table
    dim3 ggrid((VDIM + GBN - 1) / GBN, (CDIM + GBM - 1) / GBM);  // (313, 6)
    gemm_kernel<<<ggrid, 256>>>(emb, bias);

    // 3. scan + epilogue
    scan_kernel<<<BDIM, 160>>>(docs, doc_lens, wildcards, ln_gamma, ln_beta,
                               linear_w, linear_b, out);
}

// round 3
// speedup vs baseline: 1.0684x; 1.0684x over previous
#include <cuda_runtime.h>
#include <cstdint>

// ---------------------------------------------------------------------------
// SoftPatternClassifier on GB300 — mma.sync 3xTF32 GEMM + max-plus scan
//   (tcgen05 PTX rejected by harness toolchain: .target sm_103 without 'a')
//   1. split_diags_kernel : diags -> A_hi/A_lo [768 c][320 k], k-interleaved
//   2. split_emb_kernel   : E^T   -> B_hi/B_lo [20224 v][320 k], k-interleaved
//   3. gemm_mma_kernel    : table[v][c] = logsig(dot + bias) via mma.sync tf32
//   4. scan_kernel        : per-batch max-plus scan + LN/heaviside/linear
// ---------------------------------------------------------------------------

#define BDIM 64
#define LDIM 512
#define VDIM 20000
#define PDIM 150
#define CDIM 750
#define KDIM 300
#define NEGF (-1000000000.0f)

#define TSTR 752
#define KPAD 320
#define CPAD 768
#define VPAD 20224            // 158 * 128

#define TK 32                 // K floats per chunk
#define NCHUNK (KPAD / TK)    // 10
#define ASTR 40               // smem row stride (floats), conflict-free

// __device__ scratch (allocation-free rule)
__device__ float d_table[(size_t)VDIM * TSTR];   // ~60 MB
__device__ float d_Ahi[CPAD * KPAD];
__device__ float d_Alo[CPAD * KPAD];
__device__ float d_Bhi[(size_t)VPAD * KPAD];     // ~26 MB
__device__ float d_Blo[(size_t)VPAD * KPAD];     // ~26 MB

// ---------------------------------------------------------------------------
// helpers
// ---------------------------------------------------------------------------
__device__ __forceinline__ float logsig(float x) {
    return fminf(x, 0.0f) - log1pf(expf(-fabsf(x)));
}
__device__ __forceinline__ float to_tf32(float x) {
    float r;
    asm("cvt.rna.tf32.f32 %0, %1;" : "=f"(r) : "f"(x));
    return r;
}
__device__ __forceinline__ void cpa16(uint32_t dst, const void* src) {
    asm volatile("cp.async.cg.shared.global [%0], [%1], 16;" :: "r"(dst), "l"(src) : "memory");
}
#define CPA_COMMIT() asm volatile("cp.async.commit_group;" ::: "memory")
#define CPA_WAIT1()  asm volatile("cp.async.wait_group 1;" ::: "memory")
#define CPA_WAIT0()  asm volatile("cp.async.wait_group 0;" ::: "memory")

__device__ __forceinline__ uint32_t smem_u32(const void* p) {
    uint32_t a;
    asm("{ .reg .u64 t; cvta.to.shared.u64 t, %1; cvt.u32.u64 %0, t; }" : "=r"(a) : "l"(p));
    return a;
}

// k-interleave within groups of 8: original j -> slot 2*(j&3) + (j>>2)
// => stored order (0,4,1,5,2,6,3,7); thread t reads slots {2t, 2t+1} = {k=t, k=t+4}
__device__ __forceinline__ int kslot(int k) {
    int j = k & 7;
    return (k & ~7) + 2 * (j & 3) + (j >> 2);
}

__device__ __forceinline__ void mma1688(float* d, const uint32_t* a, const uint32_t* b) {
    asm volatile(
        "mma.sync.aligned.m16n8k8.row.col.f32.tf32.tf32.f32 "
        "{%0,%1,%2,%3}, {%4,%5,%6,%7}, {%8,%9}, {%0,%1,%2,%3};"
        : "+f"(d[0]), "+f"(d[1]), "+f"(d[2]), "+f"(d[3])
        : "r"(a[0]), "r"(a[1]), "r"(a[2]), "r"(a[3]), "r"(b[0]), "r"(b[1]));
}

// ---------------------------------------------------------------------------
// 1. split diags -> tf32 hi/lo, [CPAD][KPAD], k-interleaved
// ---------------------------------------------------------------------------
__global__ void split_diags_kernel(const float* __restrict__ diags) {
    int i = blockIdx.x * blockDim.x + threadIdx.x;
    if (i >= CPAD * KPAD) return;
    int c = i / KPAD;
    int k = i - c * KPAD;
    float hi = 0.0f, lo = 0.0f;
    if (c < CDIM && k < KDIM) {
        float x = diags[((c / 5) * 6 + (c % 5)) * KDIM + k];
        hi = to_tf32(x);
        lo = to_tf32(x - hi);
    }
    int dst = c * KPAD + kslot(k);
    d_Ahi[dst] = hi;
    d_Alo[dst] = lo;
}

// ---------------------------------------------------------------------------
// 2. transpose+split E [300][20000] -> B_hi/B_lo [VPAD][KPAD], k-interleaved
// ---------------------------------------------------------------------------
__global__ void split_emb_kernel(const float* __restrict__ E) {
    __shared__ float tile[32][33];
    int vt = blockIdx.x * 32;
    int kt = blockIdx.y * 32;
    int tx = threadIdx.x, ty = threadIdx.y;
#pragma unroll
    for (int r = 0; r < 4; r++) {
        int k = kt + ty + r * 8, v = vt + tx;
        tile[ty + r * 8][tx] = (k < KDIM && v < VDIM) ? E[(size_t)k * VDIM + v] : 0.0f;
    }
    __syncthreads();
#pragma unroll
    for (int r = 0; r < 4; r++) {
        int v = vt + ty + r * 8, k = kt + tx;
        float x = tile[tx][ty + r * 8];
        float hi = to_tf32(x);
        float lo = to_tf32(x - hi);
        size_t o = (size_t)v * KPAD + kslot(k);
        d_Bhi[o] = hi;
        d_Blo[o] = lo;
    }
}

// ---------------------------------------------------------------------------
// 3. GEMM via mma.sync m16n8k8 tf32, 3x split.
//    CTA: 128 v x 128 c, 256 thr (8 warps, 4(m) x 2(n), warp = 32v x 64c).
//    K: 10 chunks of 32 floats, double-buffered cp.async.
// ---------------------------------------------------------------------------
#define ARR_BYTES  (128 * ASTR * 4)            // 20480
#define STAGE_BYTES (4 * ARR_BYTES)            // 81920
#define GSMEM_TOTAL (2 * STAGE_BYTES)          // 163840
#define OFF_AH 0
#define OFF_AL ARR_BYTES
#define OFF_BH (2 * ARR_BYTES)
#define OFF_BL (3 * ARR_BYTES)

__global__ void __launch_bounds__(256, 1)
gemm_mma_kernel(const float* __restrict__ bias) {
    extern __shared__ __align__(16) char smem[];
    const uint32_t sb = smem_u32(smem);

    const int tid = threadIdx.x;
    const int wid = tid >> 5;
    const int lid = tid & 31;
    const int g   = lid >> 2;       // 0..7
    const int t   = lid & 3;        // 0..3
    const int wm  = (wid & 3) * 32; // warp m (v) offset in tile
    const int wn  = (wid >> 2) * 64;// warp n (c) offset in tile

    const int vBase = blockIdx.x * 128;
    const int cBase = blockIdx.y * 128;

    const float* gBh = d_Bhi + (size_t)vBase * KPAD;   // A operand (m = v)
    const float* gBl = d_Blo + (size_t)vBase * KPAD;
    const float* gAh = d_Ahi + (size_t)cBase * KPAD;   // B operand (n = c)
    const float* gAl = d_Alo + (size_t)cBase * KPAD;

    auto load_chunk = [&](int kc, int s) {
        const uint32_t st = sb + s * STAGE_BYTES;
        const int k0 = kc * TK;
#pragma unroll
        for (int it = 0; it < 4; it++) {
            int idx = tid + it * 256;         // 0..1023
            int r = idx >> 3, q = (idx & 7) * 4;
            uint32_t so = (uint32_t)(r * ASTR + q) * 4;
            size_t go = (size_t)r * KPAD + k0 + q;
            cpa16(st + OFF_AH + so, gBh + go);   // m-side (v rows)
            cpa16(st + OFF_AL + so, gBl + go);
            cpa16(st + OFF_BH + so, gAh + go);   // n-side (c rows)
            cpa16(st + OFF_BL + so, gAl + go);
        }
        CPA_COMMIT();
    };

    float acc[2][8][4];
#pragma unroll
    for (int mi = 0; mi < 2; mi++)
#pragma unroll
        for (int ni = 0; ni < 8; ni++)
#pragma unroll
            for (int e = 0; e < 4; e++) acc[mi][ni][e] = 0.0f;

    load_chunk(0, 0);
    load_chunk(1, 1);

    for (int i = 0; i < NCHUNK; i++) {
        const int s = i & 1;
        if (i + 1 < NCHUNK) { CPA_WAIT1(); } else { CPA_WAIT0(); }
        __syncthreads();

        const float* sAh = (const float*)(smem + s * STAGE_BYTES + OFF_AH);
        const float* sAl = (const float*)(smem + s * STAGE_BYTES + OFF_AL);
        const float* sBh = (const float*)(smem + s * STAGE_BYTES + OFF_BH);
        const float* sBl = (const float*)(smem + s * STAGE_BYTES + OFF_BL);

#pragma unroll
        for (int ks = 0; ks < 4; ks++) {
            const int kcol = ks * 8 + 2 * t;

            uint32_t Ah[2][4], Al[2][4];
#pragma unroll
            for (int mi = 0; mi < 2; mi++) {
                int r0 = wm + mi * 16 + g;
                float2 h0 = *(const float2*)&sAh[r0 * ASTR + kcol];
                float2 h1 = *(const float2*)&sAh[(r0 + 8) * ASTR + kcol];
                float2 l0 = *(const float2*)&sAl[r0 * ASTR + kcol];
                float2 l1 = *(const float2*)&sAl[(r0 + 8) * ASTR + kcol];
                Ah[mi][0] = __float_as_uint(h0.x); Ah[mi][2] = __float_as_uint(h0.y);
                Ah[mi][1] = __float_as_uint(h1.x); Ah[mi][3] = __float_as_uint(h1.y);
                Al[mi][0] = __float_as_uint(l0.x); Al[mi][2] = __float_as_uint(l0.y);
                Al[mi][1] = __float_as_uint(l1.x); Al[mi][3] = __float_as_uint(l1.y);
            }
            uint32_t Bh[8][2], Bl[8][2];
#pragma unroll
            for (int ni = 0; ni < 8; ni++) {
                int rn = wn + ni * 8 + g;
                float2 h = *(const float2*)&sBh[rn * ASTR + kcol];
                float2 l = *(const float2*)&sBl[rn * ASTR + kcol];
                Bh[ni][0] = __float_as_uint(h.x); Bh[ni][1] = __float_as_uint(h.y);
                Bl[ni][0] = __float_as_uint(l.x); Bl[ni][1] = __float_as_uint(l.y);
            }
#pragma unroll
            for (int mi = 0; mi < 2; mi++)
#pragma unroll
                for (int ni = 0; ni < 8; ni++) {
                    mma1688(acc[mi][ni], Ah[mi], Bh[ni]);
                    mma1688(acc[mi][ni], Ah[mi], Bl[ni]);
                    mma1688(acc[mi][ni], Al[mi], Bh[ni]);
                }
        }
        __syncthreads();
        if (i + 2 < NCHUNK) load_chunk(i + 2, s);
    }

    // ---- epilogue: +bias, logsig, store float2 to table[v][c] ----
#pragma unroll
    for (int ni = 0; ni < 8; ni++) {
        const int c = cBase + wn + ni * 8 + 2 * t;
        if (c >= CDIM) continue;                       // CDIM even, c even
        const float b0 = __ldg(&bias[(c / 5) * 6 + (c % 5)]);
        const int c1 = c + 1;
        const float b1 = __ldg(&bias[(c1 / 5) * 6 + (c1 % 5)]);
#pragma unroll
        for (int mi = 0; mi < 2; mi++) {
            const int v0 = vBase + wm + mi * 16 + g;
            const int v1 = v0 + 8;
            if (v0 < VDIM) {
                float2 r;
                r.x = logsig(acc[mi][ni][0] + b0);
                r.y = logsig(acc[mi][ni][1] + b1);
                *(float2*)&d_table[(size_t)v0 * TSTR + c] = r;
            }
            if (v1 < VDIM) {
                float2 r;
                r.x = logsig(acc[mi][ni][2] + b0);
                r.y = logsig(acc[mi][ni][3] + b1);
                *(float2*)&d_table[(size_t)v1 * TSTR + c] = r;
            }
        }
    }
}

// ---------------------------------------------------------------------------
// 4. scan (unchanged from R1 passing version)
// ---------------------------------------------------------------------------
#define PF 8

__global__ void __launch_bounds__(160)
scan_kernel(const int*   __restrict__ docs,
            const int*   __restrict__ doc_lens,
            const float* __restrict__ wildcards,
            const float* __restrict__ gamma,
            const float* __restrict__ beta,
            const float* __restrict__ W,
            const float* __restrict__ lb,
            float*       __restrict__ out) {
    const int b   = blockIdx.x;
    const int tid = threadIdx.x;
    const int p   = tid;
    const bool valid = (p < PDIM);

    __shared__ int   s_tok[LDIM];
    __shared__ float sh[192];
    __shared__ float sred[2];

    for (int i = tid; i < LDIM; i += 160) s_tok[i] = docs[b * LDIM + i];
    __syncthreads();

    float wl[5];
#pragma unroll
    for (int m = 0; m < 5; m++)
        wl[m] = valid ? logsig(__ldg(&wildcards[p * 5 + m])) : 0.0f;

    const int len    = doc_lens[b];
    const int endSel = p / 50;

    float h1 = NEGF, h2 = NEGF, h3 = NEGF, h4 = NEGF, h5 = NEGF;
    float sc = NEGF;

    float pf[PF][5];
#pragma unroll
    for (int u = 0; u < PF; u++) {
        if (valid) {
            const float* row = &d_table[(size_t)s_tok[u] * TSTR + p * 5];
#pragma unroll
            for (int m = 0; m < 5; m++) pf[u][m] = __ldg(&row[m]);
        } else {
#pragma unroll
            for (int m = 0; m < 5; m++) pf[u][m] = 0.0f;
        }
    }

    for (int t = 0; t < LDIM; t += PF) {
#pragma unroll
        for (int u = 0; u < PF; u++) {
            float e0 = fmaxf(pf[u][0], wl[0]);
            float e1 = fmaxf(pf[u][1], wl[1]);
            float e2 = fmaxf(pf[u][2], wl[2]);
            float e3 = fmaxf(pf[u][3], wl[3]);
            float e4 = fmaxf(pf[u][4], wl[4]);
            h5 = h4 + e4;
            h4 = h3 + e3;
            h3 = h2 + e2;
            h2 = h1 + e1;
            h1 = e0;
            float ev = (endSel == 0) ? h3 : ((endSel == 1) ? h4 : h5);
            int tt = t + u;
            sc = (tt < len) ? fmaxf(sc, ev) : sc;
            int nt = tt + PF;
            if (nt < LDIM && valid) {
                const float* row = &d_table[(size_t)s_tok[nt] * TSTR + p * 5];
#pragma unroll
                for (int m = 0; m < 5; m++) pf[u][m] = __ldg(&row[m]);
            }
        }
    }

    float score = valid ? expf(sc) : 0.0f;

    sh[tid] = score;
    __syncthreads();
    if (tid < 32) {
        float s = 0.0f;
        for (int i = tid; i < PDIM; i += 32) s += sh[i];
#pragma unroll
        for (int o = 16; o > 0; o >>= 1) s += __shfl_down_sync(0xffffffffu, s, o);
        if (tid == 0) sred[0] = s * (1.0f / PDIM);
    }
    __syncthreads();
    const float mu = sred[0];

    float d = score - mu;
    sh[tid] = valid ? d * d : 0.0f;
    __syncthreads();
    if (tid < 32) {
        float s = 0.0f;
        for (int i = tid; i < PDIM; i += 32) s += sh[i];
#pragma unroll
        for (int o = 16; o > 0; o >>= 1) s += __shfl_down_sync(0xffffffffu, s, o);
        if (tid == 0) sred[1] = s * (1.0f / PDIM);
    }
    __syncthreads();
    const float var = sred[1];

    float bin = 0.0f;
    if (valid) {
        float norm = (score - mu) * rsqrtf(var + 1e-5f) * __ldg(&gamma[p]) + __ldg(&beta[p]);
        bin = (norm > 0.0f) ? 1.0f : 0.0f;
    }

    sh[tid] = valid ? bin * __ldg(&W[p]) : 0.0f;
    __syncthreads();
    if (tid < 32) {
        float s = 0.0f;
        for (int i = tid; i < PDIM; i += 32) s += sh[i];
#pragma unroll
        for (int o = 16; o > 0; o >>= 1) s += __shfl_down_sync(0xffffffffu, s, o);
        if (tid == 0) out[b * 2 + 0] = s + __ldg(&lb[0]);
    }
    __syncthreads();
    sh[tid] = valid ? bin * __ldg(&W[PDIM + p]) : 0.0f;
    __syncthreads();
    if (tid < 32) {
        float s = 0.0f;
        for (int i = tid; i < PDIM; i += 32) s += sh[i];
#pragma unroll
        for (int o = 16; o > 0; o >>= 1) s += __shfl_down_sync(0xffffffffu, s, o);
        if (tid == 0) out[b * 2 + 1] = s + __ldg(&lb[1]);
    }
}

// ---------------------------------------------------------------------------
// launch
// ---------------------------------------------------------------------------
extern "C" void kernel_launch(void* const* d_in, const int* in_sizes, int n_in,
                              void* d_out, int out_size) {
    const int*   docs      = (const int*)  d_in[0];
    const int*   doc_lens  = (const int*)  d_in[1];
    const float* emb       = (const float*)d_in[2];
    const float* diags     = (const float*)d_in[3];
    const float* bias      = (const float*)d_in[4];
    const float* wildcards = (const float*)d_in[5];
    const float* ln_gamma  = (const float*)d_in[6];
    const float* ln_beta   = (const float*)d_in[7];
    const float* linear_w  = (const float*)d_in[8];
    const float* linear_b  = (const float*)d_in[9];
    float*       out       = (float*)d_out;

    (void)in_sizes; (void)n_in; (void)out_size;

    cudaFuncSetAttribute(gemm_mma_kernel,
                         cudaFuncAttributeMaxDynamicSharedMemorySize, GSMEM_TOTAL);

    split_diags_kernel<<<(CPAD * KPAD + 255) / 256, 256>>>(diags);

    dim3 tgrid(VPAD / 32, KPAD / 32);        // (632, 10)
    split_emb_kernel<<<tgrid, dim3(32, 8)>>>(emb);

    dim3 ggrid(VPAD / 128, CPAD / 128);      // (158, 6)
    gemm_mma_kernel<<<ggrid, 256, GSMEM_TOTAL>>>(bias);

    scan_kernel<<<BDIM, 160>>>(docs, doc_lens, wildcards, ln_gamma, ln_beta,
                               linear_w, linear_b, out);
}

// round 6
// speedup vs baseline: 1.4452x; 1.3526x over previous
#include <cuda_runtime.h>
#include <cstdint>

// ---------------------------------------------------------------------------
// SoftPatternClassifier on GB300 — mma.sync 3xTF32 GEMM + chunked window scan
//   1. split_diags_kernel : diags -> A_hi/A_lo [768 c][320 k], k-interleaved
//   2. split_emb_kernel   : E^T   -> B_hi/B_lo [20224 v][320 k], k-interleaved
//   3. gemm_mma_kernel    : table[v][c] = logsig(dot + bias) via mma.sync tf32
//   4. scan_part_kernel   : (b, chunk) partial max over 64 positions (+4 warmup)
//   5. scan_final_kernel  : reduce chunks + exp/LN/heaviside/linear epilogue
// ---------------------------------------------------------------------------

#define BDIM 64
#define LDIM 512
#define VDIM 20000
#define PDIM 150
#define CDIM 750
#define KDIM 300
#define NEGF (-1000000000.0f)

#define TSTR 752
#define KPAD 320
#define CPAD 768
#define VPAD 20224            // 158 * 128

#define TK 32                 // K floats per chunk
#define NCHUNK (KPAD / TK)    // 10
#define ASTR 40               // smem row stride (floats), conflict-free

#define NSC 8                 // scan time-chunks
#define SCT 64                // positions per scan chunk

// __device__ scratch (allocation-free rule)
__device__ float d_table[(size_t)VDIM * TSTR];   // ~60 MB
__device__ float d_Ahi[CPAD * KPAD];
__device__ float d_Alo[CPAD * KPAD];
__device__ float d_Bhi[(size_t)VPAD * KPAD];     // ~26 MB
__device__ float d_Blo[(size_t)VPAD * KPAD];     // ~26 MB
__device__ float d_part[BDIM][NSC][160];

// ---------------------------------------------------------------------------
// helpers
// ---------------------------------------------------------------------------
__device__ __forceinline__ float logsig(float x) {
    return fminf(x, 0.0f) - log1pf(expf(-fabsf(x)));
}
__device__ __forceinline__ float to_tf32(float x) {
    float r;
    asm("cvt.rna.tf32.f32 %0, %1;" : "=f"(r) : "f"(x));
    return r;
}
__device__ __forceinline__ void cpa16(uint32_t dst, const void* src) {
    asm volatile("cp.async.cg.shared.global [%0], [%1], 16;" :: "r"(dst), "l"(src) : "memory");
}
#define CPA_COMMIT() asm volatile("cp.async.commit_group;" ::: "memory")
#define CPA_WAIT1()  asm volatile("cp.async.wait_group 1;" ::: "memory")
#define CPA_WAIT0()  asm volatile("cp.async.wait_group 0;" ::: "memory")

__device__ __forceinline__ uint32_t smem_u32(const void* p) {
    uint32_t a;
    asm("{ .reg .u64 t; cvta.to.shared.u64 t, %1; cvt.u32.u64 %0, t; }" : "=r"(a) : "l"(p));
    return a;
}

// k-interleave within groups of 8: stored order (0,4,1,5,2,6,3,7)
__device__ __forceinline__ int kslot(int k) {
    int j = k & 7;
    return (k & ~7) + 2 * (j & 3) + (j >> 2);
}

__device__ __forceinline__ void mma1688(float* d, const uint32_t* a, const uint32_t* b) {
    asm volatile(
        "mma.sync.aligned.m16n8k8.row.col.f32.tf32.tf32.f32 "
        "{%0,%1,%2,%3}, {%4,%5,%6,%7}, {%8,%9}, {%0,%1,%2,%3};"
        : "+f"(d[0]), "+f"(d[1]), "+f"(d[2]), "+f"(d[3])
        : "r"(a[0]), "r"(a[1]), "r"(a[2]), "r"(a[3]), "r"(b[0]), "r"(b[1]));
}

// ---------------------------------------------------------------------------
// 1. split diags -> tf32 hi/lo, [CPAD][KPAD], k-interleaved
// ---------------------------------------------------------------------------
__global__ void split_diags_kernel(const float* __restrict__ diags) {
    int i = blockIdx.x * blockDim.x + threadIdx.x;
    if (i >= CPAD * KPAD) return;
    int c = i / KPAD;
    int k = i - c * KPAD;
    float hi = 0.0f, lo = 0.0f;
    if (c < CDIM && k < KDIM) {
        float x = diags[((c / 5) * 6 + (c % 5)) * KDIM + k];
        hi = to_tf32(x);
        lo = to_tf32(x - hi);
    }
    int dst = c * KPAD + kslot(k);
    d_Ahi[dst] = hi;
    d_Alo[dst] = lo;
}

// ---------------------------------------------------------------------------
// 2. transpose+split E [300][20000] -> B_hi/B_lo [VPAD][KPAD], k-interleaved
// ---------------------------------------------------------------------------
__global__ void split_emb_kernel(const float* __restrict__ E) {
    __shared__ float tile[32][33];
    int vt = blockIdx.x * 32;
    int kt = blockIdx.y * 32;
    int tx = threadIdx.x, ty = threadIdx.y;
#pragma unroll
    for (int r = 0; r < 4; r++) {
        int k = kt + ty + r * 8, v = vt + tx;
        tile[ty + r * 8][tx] = (k < KDIM && v < VDIM) ? E[(size_t)k * VDIM + v] : 0.0f;
    }
    __syncthreads();
#pragma unroll
    for (int r = 0; r < 4; r++) {
        int v = vt + ty + r * 8, k = kt + tx;
        float x = tile[tx][ty + r * 8];
        float hi = to_tf32(x);
        float lo = to_tf32(x - hi);
        size_t o = (size_t)v * KPAD + kslot(k);
        d_Bhi[o] = hi;
        d_Blo[o] = lo;
    }
}

// ---------------------------------------------------------------------------
// 3. GEMM via mma.sync m16n8k8 tf32, 3x split.
//    CTA: 128 v x 128 c, 256 thr (8 warps, 4(m) x 2(n), warp = 32v x 64c).
// ---------------------------------------------------------------------------
#define ARR_BYTES  (128 * ASTR * 4)            // 20480
#define STAGE_BYTES (4 * ARR_BYTES)            // 81920
#define GSMEM_TOTAL (2 * STAGE_BYTES)          // 163840
#define OFF_AH 0
#define OFF_AL ARR_BYTES
#define OFF_BH (2 * ARR_BYTES)
#define OFF_BL (3 * ARR_BYTES)

__global__ void __launch_bounds__(256, 1)
gemm_mma_kernel(const float* __restrict__ bias) {
    extern __shared__ __align__(16) char smem[];
    const uint32_t sb = smem_u32(smem);

    const int tid = threadIdx.x;
    const int wid = tid >> 5;
    const int lid = tid & 31;
    const int g   = lid >> 2;       // 0..7
    const int t   = lid & 3;        // 0..3
    const int wm  = (wid & 3) * 32;
    const int wn  = (wid >> 2) * 64;

    const int vBase = blockIdx.x * 128;
    const int cBase = blockIdx.y * 128;

    const float* gBh = d_Bhi + (size_t)vBase * KPAD;
    const float* gBl = d_Blo + (size_t)vBase * KPAD;
    const float* gAh = d_Ahi + (size_t)cBase * KPAD;
    const float* gAl = d_Alo + (size_t)cBase * KPAD;

    auto load_chunk = [&](int kc, int s) {
        const uint32_t st = sb + s * STAGE_BYTES;
        const int k0 = kc * TK;
#pragma unroll
        for (int it = 0; it < 4; it++) {
            int idx = tid + it * 256;
            int r = idx >> 3, q = (idx & 7) * 4;
            uint32_t so = (uint32_t)(r * ASTR + q) * 4;
            size_t go = (size_t)r * KPAD + k0 + q;
            cpa16(st + OFF_AH + so, gBh + go);
            cpa16(st + OFF_AL + so, gBl + go);
            cpa16(st + OFF_BH + so, gAh + go);
            cpa16(st + OFF_BL + so, gAl + go);
        }
        CPA_COMMIT();
    };

    float acc[2][8][4];
#pragma unroll
    for (int mi = 0; mi < 2; mi++)
#pragma unroll
        for (int ni = 0; ni < 8; ni++)
#pragma unroll
            for (int e = 0; e < 4; e++) acc[mi][ni][e] = 0.0f;

    load_chunk(0, 0);
    load_chunk(1, 1);

    for (int i = 0; i < NCHUNK; i++) {
        const int s = i & 1;
        if (i + 1 < NCHUNK) { CPA_WAIT1(); } else { CPA_WAIT0(); }
        __syncthreads();

        const float* sAh = (const float*)(smem + s * STAGE_BYTES + OFF_AH);
        const float* sAl = (const float*)(smem + s * STAGE_BYTES + OFF_AL);
        const float* sBh = (const float*)(smem + s * STAGE_BYTES + OFF_BH);
        const float* sBl = (const float*)(smem + s * STAGE_BYTES + OFF_BL);

#pragma unroll
        for (int ks = 0; ks < 4; ks++) {
            const int kcol = ks * 8 + 2 * t;

            uint32_t Ah[2][4], Al[2][4];
#pragma unroll
            for (int mi = 0; mi < 2; mi++) {
                int r0 = wm + mi * 16 + g;
                float2 h0 = *(const float2*)&sAh[r0 * ASTR + kcol];
                float2 h1 = *(const float2*)&sAh[(r0 + 8) * ASTR + kcol];
                float2 l0 = *(const float2*)&sAl[r0 * ASTR + kcol];
                float2 l1 = *(const float2*)&sAl[(r0 + 8) * ASTR + kcol];
                Ah[mi][0] = __float_as_uint(h0.x); Ah[mi][2] = __float_as_uint(h0.y);
                Ah[mi][1] = __float_as_uint(h1.x); Ah[mi][3] = __float_as_uint(h1.y);
                Al[mi][0] = __float_as_uint(l0.x); Al[mi][2] = __float_as_uint(l0.y);
                Al[mi][1] = __float_as_uint(l1.x); Al[mi][3] = __float_as_uint(l1.y);
            }
            uint32_t Bh[8][2], Bl[8][2];
#pragma unroll
            for (int ni = 0; ni < 8; ni++) {
                int rn = wn + ni * 8 + g;
                float2 h = *(const float2*)&sBh[rn * ASTR + kcol];
                float2 l = *(const float2*)&sBl[rn * ASTR + kcol];
                Bh[ni][0] = __float_as_uint(h.x); Bh[ni][1] = __float_as_uint(h.y);
                Bl[ni][0] = __float_as_uint(l.x); Bl[ni][1] = __float_as_uint(l.y);
            }
#pragma unroll
            for (int mi = 0; mi < 2; mi++)
#pragma unroll
                for (int ni = 0; ni < 8; ni++) {
                    mma1688(acc[mi][ni], Ah[mi], Bh[ni]);
                    mma1688(acc[mi][ni], Ah[mi], Bl[ni]);
                    mma1688(acc[mi][ni], Al[mi], Bh[ni]);
                }
        }
        __syncthreads();
        if (i + 2 < NCHUNK) load_chunk(i + 2, s);
    }

    // ---- epilogue: +bias, logsig, float2 stores to table[v][c] ----
#pragma unroll
    for (int ni = 0; ni < 8; ni++) {
        const int c = cBase + wn + ni * 8 + 2 * t;
        if (c >= CDIM) continue;
        const float b0 = __ldg(&bias[(c / 5) * 6 + (c % 5)]);
        const int c1 = c + 1;
        const float b1 = __ldg(&bias[(c1 / 5) * 6 + (c1 % 5)]);
#pragma unroll
        for (int mi = 0; mi < 2; mi++) {
            const int v0 = vBase + wm + mi * 16 + g;
            const int v1 = v0 + 8;
            if (v0 < VDIM) {
                float2 r;
                r.x = logsig(acc[mi][ni][0] + b0);
                r.y = logsig(acc[mi][ni][1] + b1);
                *(float2*)&d_table[(size_t)v0 * TSTR + c] = r;
            }
            if (v1 < VDIM) {
                float2 r;
                r.x = logsig(acc[mi][ni][2] + b0);
                r.y = logsig(acc[mi][ni][3] + b1);
                *(float2*)&d_table[(size_t)v1 * TSTR + c] = r;
            }
        }
    }
}

// ---------------------------------------------------------------------------
// 4. chunked scan: block (b, ch) handles positions [ch*64, ch*64+64) with a
//    4-token warmup (hid[m](t) is a sliding-window sum of depth <= 5).
// ---------------------------------------------------------------------------
__global__ void __launch_bounds__(160)
scan_part_kernel(const int*   __restrict__ docs,
                 const int*   __restrict__ doc_lens,
                 const float* __restrict__ wildcards) {
    const int b   = blockIdx.x;
    const int ch  = blockIdx.y;
    const int tid = threadIdx.x;
    const int p   = tid;
    const bool valid = (p < PDIM);

    const int len = doc_lens[b];
    const int c0  = ch * SCT;
    if (len <= c0) {                 // chunk entirely past doc end
        if (valid) d_part[b][ch][p] = NEGF;
        return;
    }

    const int warm   = (ch == 0) ? 0 : 4;
    const int tstart = c0 - warm;
    const int nt     = warm + SCT;   // 64 or 68 (both %4 == 0)

    __shared__ int s_tok[SCT + 4];
    for (int i = tid; i < nt; i += 160) s_tok[i] = docs[b * LDIM + tstart + i];
    __syncthreads();

    float wl[5];
#pragma unroll
    for (int m = 0; m < 5; m++)
        wl[m] = valid ? logsig(__ldg(&wildcards[p * 5 + m])) : 0.0f;

    const int endSel = p / 50;
    float h1 = NEGF, h2 = NEGF, h3 = NEGF, h4 = NEGF, h5 = NEGF;
    float sc = NEGF;

    float pf[4][5];
#pragma unroll
    for (int u = 0; u < 4; u++) {
        if (valid && u < nt) {
            const float* row = &d_table[(size_t)s_tok[u] * TSTR + p * 5];
#pragma unroll
            for (int m = 0; m < 5; m++) pf[u][m] = __ldg(&row[m]);
        } else {
#pragma unroll
            for (int m = 0; m < 5; m++) pf[u][m] = 0.0f;
        }
    }

    const int scoreLo = warm;                      // local index of c0
    const int scoreHi = (len < c0 + SCT ? len : c0 + SCT) - tstart;

    for (int i = 0; i < nt; i += 4) {
#pragma unroll
        for (int u = 0; u < 4; u++) {
            float e0 = fmaxf(pf[u][0], wl[0]);
            float e1 = fmaxf(pf[u][1], wl[1]);
            float e2 = fmaxf(pf[u][2], wl[2]);
            float e3 = fmaxf(pf[u][3], wl[3]);
            float e4 = fmaxf(pf[u][4], wl[4]);
            h5 = h4 + e4;
            h4 = h3 + e3;
            h3 = h2 + e2;
            h2 = h1 + e1;
            h1 = e0;
            float ev = (endSel == 0) ? h3 : ((endSel == 1) ? h4 : h5);
            int li = i + u;
            sc = (li >= scoreLo && li < scoreHi) ? fmaxf(sc, ev) : sc;
            int ni = li + 4;
            if (ni < nt && valid) {
                const float* row = &d_table[(size_t)s_tok[ni] * TSTR + p * 5];
#pragma unroll
                for (int m = 0; m < 5; m++) pf[u][m] = __ldg(&row[m]);
            }
        }
    }

    if (valid) d_part[b][ch][p] = sc;
}

// ---------------------------------------------------------------------------
// 5. final: reduce chunks, exp/LN/heaviside/linear
// ---------------------------------------------------------------------------
__global__ void __launch_bounds__(160)
scan_final_kernel(const float* __restrict__ gamma,
                  const float* __restrict__ beta,
                  const float* __restrict__ W,
                  const float* __restrict__ lb,
                  float*       __restrict__ out) {
    const int b   = blockIdx.x;
    const int tid = threadIdx.x;
    const bool valid = (tid < PDIM);

    __shared__ float sh[192];
    __shared__ float sred[2];

    float sc = NEGF;
    if (valid) {
#pragma unroll
        for (int ch = 0; ch < NSC; ch++) sc = fmaxf(sc, d_part[b][ch][tid]);
    }
    float score = valid ? expf(sc) : 0.0f;

    sh[tid] = score;
    __syncthreads();
    if (tid < 32) {
        float s = 0.0f;
        for (int i = tid; i < PDIM; i += 32) s += sh[i];
#pragma unroll
        for (int o = 16; o > 0; o >>= 1) s += __shfl_down_sync(0xffffffffu, s, o);
        if (tid == 0) sred[0] = s * (1.0f / PDIM);
    }
    __syncthreads();
    const float mu = sred[0];

    float d = score - mu;
    sh[tid] = valid ? d * d : 0.0f;
    __syncthreads();
    if (tid < 32) {
        float s = 0.0f;
        for (int i = tid; i < PDIM; i += 32) s += sh[i];
#pragma unroll
        for (int o = 16; o > 0; o >>= 1) s += __shfl_down_sync(0xffffffffu, s, o);
        if (tid == 0) sred[1] = s * (1.0f / PDIM);
    }
    __syncthreads();
    const float var = sred[1];

    float bin = 0.0f;
    if (valid) {
        float norm = (score - mu) * rsqrtf(var + 1e-5f) * __ldg(&gamma[tid]) + __ldg(&beta[tid]);
        bin = (norm > 0.0f) ? 1.0f : 0.0f;
    }

    sh[tid] = valid ? bin * __ldg(&W[tid]) : 0.0f;
    __syncthreads();
    if (tid < 32) {
        float s = 0.0f;
        for (int i = tid; i < PDIM; i += 32) s += sh[i];
#pragma unroll
        for (int o = 16; o > 0; o >>= 1) s += __shfl_down_sync(0xffffffffu, s, o);
        if (tid == 0) out[b * 2 + 0] = s + __ldg(&lb[0]);
    }
    __syncthreads();
    sh[tid] = valid ? bin * __ldg(&W[PDIM + tid]) : 0.0f;
    __syncthreads();
    if (tid < 32) {
        float s = 0.0f;
        for (int i = tid; i < PDIM; i += 32) s += sh[i];
#pragma unroll
        for (int o = 16; o > 0; o >>= 1) s += __shfl_down_sync(0xffffffffu, s, o);
        if (tid == 0) out[b * 2 + 1] = s + __ldg(&lb[1]);
    }
}

// ---------------------------------------------------------------------------
// launch
// ---------------------------------------------------------------------------
extern "C" void kernel_launch(void* const* d_in, const int* in_sizes, int n_in,
                              void* d_out, int out_size) {
    const int*   docs      = (const int*)  d_in[0];
    const int*   doc_lens  = (const int*)  d_in[1];
    const float* emb       = (const float*)d_in[2];
    const float* diags     = (const float*)d_in[3];
    const float* bias      = (const float*)d_in[4];
    const float* wildcards = (const float*)d_in[5];
    const float* ln_gamma  = (const float*)d_in[6];
    const float* ln_beta   = (const float*)d_in[7];
    const float* linear_w  = (const float*)d_in[8];
    const float* linear_b  = (const float*)d_in[9];
    float*       out       = (float*)d_out;

    (void)in_sizes; (void)n_in; (void)out_size;

    cudaFuncSetAttribute(gemm_mma_kernel,
                         cudaFuncAttributeMaxDynamicSharedMemorySize, GSMEM_TOTAL);

    split_diags_kernel<<<(CPAD * KPAD + 255) / 256, 256>>>(diags);

    dim3 tgrid(VPAD / 32, KPAD / 32);        // (632, 10)
    split_emb_kernel<<<tgrid, dim3(32, 8)>>>(emb);

    dim3 ggrid(VPAD / 128, CPAD / 128);      // (158, 6)
    gemm_mma_kernel<<<ggrid, 256, GSMEM_TOTAL>>>(bias);

    dim3 sgrid(BDIM, NSC);                   // (64, 8)
    scan_part_kernel<<<sgrid, 160>>>(docs, doc_lens, wildcards);

    scan_final_kernel<<<BDIM, 160>>>(ln_gamma, ln_beta, linear_w, linear_b, out);
}

// round 7
// speedup vs baseline: 1.4489x; 1.0026x over previous
#include <cuda_runtime.h>
#include <cstdint>

// ---------------------------------------------------------------------------
// SoftPatternClassifier on GB300 — mma.sync 3xTF32 GEMM + chunked window scan
//   R7: GEMM TK=16/ASTR=24/KPAD=304, 2 CTAs/SM; scan chunks 16x32.
// ---------------------------------------------------------------------------

#define BDIM 64
#define LDIM 512
#define VDIM 20000
#define PDIM 150
#define CDIM 750
#define KDIM 300
#define NEGF (-1000000000.0f)

#define TSTR 752
#define KPAD 304              // 19 * 16
#define CPAD 768
#define VPAD 20224            // 158 * 128

#define TK 16                 // K floats per chunk
#define NCHUNK (KPAD / TK)    // 19
#define ASTR 24               // smem row stride (floats), conflict-free

#define NSC 16                // scan time-chunks
#define SCT 32                // positions per scan chunk

// __device__ scratch (allocation-free rule)
__device__ float d_table[(size_t)VDIM * TSTR];   // ~60 MB
__device__ float d_Ahi[CPAD * KPAD];
__device__ float d_Alo[CPAD * KPAD];
__device__ float d_Bhi[(size_t)VPAD * KPAD];     // ~24.6 MB
__device__ float d_Blo[(size_t)VPAD * KPAD];     // ~24.6 MB
__device__ float d_part[BDIM][NSC][160];

// ---------------------------------------------------------------------------
// helpers
// ---------------------------------------------------------------------------
__device__ __forceinline__ float logsig(float x) {
    return fminf(x, 0.0f) - log1pf(expf(-fabsf(x)));
}
__device__ __forceinline__ float to_tf32(float x) {
    float r;
    asm("cvt.rna.tf32.f32 %0, %1;" : "=f"(r) : "f"(x));
    return r;
}
__device__ __forceinline__ void cpa16(uint32_t dst, const void* src) {
    asm volatile("cp.async.cg.shared.global [%0], [%1], 16;" :: "r"(dst), "l"(src) : "memory");
}
#define CPA_COMMIT() asm volatile("cp.async.commit_group;" ::: "memory")
#define CPA_WAIT1()  asm volatile("cp.async.wait_group 1;" ::: "memory")
#define CPA_WAIT0()  asm volatile("cp.async.wait_group 0;" ::: "memory")

__device__ __forceinline__ uint32_t smem_u32(const void* p) {
    uint32_t a;
    asm("{ .reg .u64 t; cvta.to.shared.u64 t, %1; cvt.u32.u64 %0, t; }" : "=r"(a) : "l"(p));
    return a;
}

// k-interleave within groups of 8: stored order (0,4,1,5,2,6,3,7)
__device__ __forceinline__ int kslot(int k) {
    int j = k & 7;
    return (k & ~7) + 2 * (j & 3) + (j >> 2);
}

__device__ __forceinline__ void mma1688(float* d, const uint32_t* a, const uint32_t* b) {
    asm volatile(
        "mma.sync.aligned.m16n8k8.row.col.f32.tf32.tf32.f32 "
        "{%0,%1,%2,%3}, {%4,%5,%6,%7}, {%8,%9}, {%0,%1,%2,%3};"
        : "+f"(d[0]), "+f"(d[1]), "+f"(d[2]), "+f"(d[3])
        : "r"(a[0]), "r"(a[1]), "r"(a[2]), "r"(a[3]), "r"(b[0]), "r"(b[1]));
}

// ---------------------------------------------------------------------------
// 1. split diags -> tf32 hi/lo, [CPAD][KPAD], k-interleaved
// ---------------------------------------------------------------------------
__global__ void split_diags_kernel(const float* __restrict__ diags) {
    int i = blockIdx.x * blockDim.x + threadIdx.x;
    if (i >= CPAD * KPAD) return;
    int c = i / KPAD;
    int k = i - c * KPAD;
    float hi = 0.0f, lo = 0.0f;
    if (c < CDIM && k < KDIM) {
        float x = diags[((c / 5) * 6 + (c % 5)) * KDIM + k];
        hi = to_tf32(x);
        lo = to_tf32(x - hi);
    }
    int dst = c * KPAD + kslot(k);
    d_Ahi[dst] = hi;
    d_Alo[dst] = lo;
}

// ---------------------------------------------------------------------------
// 2. transpose+split E [300][20000] -> B_hi/B_lo [VPAD][KPAD], k-interleaved
// ---------------------------------------------------------------------------
__global__ void split_emb_kernel(const float* __restrict__ E) {
    __shared__ float tile[32][33];
    int vt = blockIdx.x * 32;
    int kt = blockIdx.y * 32;
    int tx = threadIdx.x, ty = threadIdx.y;
#pragma unroll
    for (int r = 0; r < 4; r++) {
        int k = kt + ty + r * 8, v = vt + tx;
        tile[ty + r * 8][tx] = (k < KDIM && v < VDIM) ? E[(size_t)k * VDIM + v] : 0.0f;
    }
    __syncthreads();
#pragma unroll
    for (int r = 0; r < 4; r++) {
        int v = vt + ty + r * 8, k = kt + tx;
        if (k >= KPAD) continue;
        float x = tile[tx][ty + r * 8];
        float hi = to_tf32(x);
        float lo = to_tf32(x - hi);
        size_t o = (size_t)v * KPAD + kslot(k);
        d_Bhi[o] = hi;
        d_Blo[o] = lo;
    }
}

// ---------------------------------------------------------------------------
// 3. GEMM via mma.sync m16n8k8 tf32, 3x split.
//    CTA: 128 v x 128 c, 256 thr (8 warps, 4(m) x 2(n), warp = 32v x 64c).
//    K: 19 chunks of 16 floats, double-buffered cp.async, 2 CTAs/SM.
// ---------------------------------------------------------------------------
#define ARR_BYTES  (128 * ASTR * 4)            // 12288
#define STAGE_BYTES (4 * ARR_BYTES)            // 49152
#define GSMEM_TOTAL (2 * STAGE_BYTES)          // 98304
#define OFF_AH 0
#define OFF_AL ARR_BYTES
#define OFF_BH (2 * ARR_BYTES)
#define OFF_BL (3 * ARR_BYTES)

__global__ void __launch_bounds__(256, 2)
gemm_mma_kernel(const float* __restrict__ bias) {
    extern __shared__ __align__(16) char smem[];
    const uint32_t sb = smem_u32(smem);

    const int tid = threadIdx.x;
    const int wid = tid >> 5;
    const int lid = tid & 31;
    const int g   = lid >> 2;       // 0..7
    const int t   = lid & 3;        // 0..3
    const int wm  = (wid & 3) * 32;
    const int wn  = (wid >> 2) * 64;

    const int vBase = blockIdx.x * 128;
    const int cBase = blockIdx.y * 128;

    const float* gBh = d_Bhi + (size_t)vBase * KPAD;
    const float* gBl = d_Blo + (size_t)vBase * KPAD;
    const float* gAh = d_Ahi + (size_t)cBase * KPAD;
    const float* gAl = d_Alo + (size_t)cBase * KPAD;

    auto load_chunk = [&](int kc, int s) {
        const uint32_t st = sb + s * STAGE_BYTES;
        const int k0 = kc * TK;
#pragma unroll
        for (int it = 0; it < 2; it++) {
            int idx = tid + it * 256;           // 0..511
            int r = idx >> 2, q = (idx & 3) * 4;
            uint32_t so = (uint32_t)(r * ASTR + q) * 4;
            size_t go = (size_t)r * KPAD + k0 + q;
            cpa16(st + OFF_AH + so, gBh + go);
            cpa16(st + OFF_AL + so, gBl + go);
            cpa16(st + OFF_BH + so, gAh + go);
            cpa16(st + OFF_BL + so, gAl + go);
        }
        CPA_COMMIT();
    };

    float acc[2][8][4];
#pragma unroll
    for (int mi = 0; mi < 2; mi++)
#pragma unroll
        for (int ni = 0; ni < 8; ni++)
#pragma unroll
            for (int e = 0; e < 4; e++) acc[mi][ni][e] = 0.0f;

    load_chunk(0, 0);
    load_chunk(1, 1);

    for (int i = 0; i < NCHUNK; i++) {
        const int s = i & 1;
        if (i + 1 < NCHUNK) { CPA_WAIT1(); } else { CPA_WAIT0(); }
        __syncthreads();

        const float* sAh = (const float*)(smem + s * STAGE_BYTES + OFF_AH);
        const float* sAl = (const float*)(smem + s * STAGE_BYTES + OFF_AL);
        const float* sBh = (const float*)(smem + s * STAGE_BYTES + OFF_BH);
        const float* sBl = (const float*)(smem + s * STAGE_BYTES + OFF_BL);

#pragma unroll
        for (int ks = 0; ks < 2; ks++) {
            const int kcol = ks * 8 + 2 * t;

            uint32_t Ah[2][4], Al[2][4];
#pragma unroll
            for (int mi = 0; mi < 2; mi++) {
                int r0 = wm + mi * 16 + g;
                float2 h0 = *(const float2*)&sAh[r0 * ASTR + kcol];
                float2 h1 = *(const float2*)&sAh[(r0 + 8) * ASTR + kcol];
                float2 l0 = *(const float2*)&sAl[r0 * ASTR + kcol];
                float2 l1 = *(const float2*)&sAl[(r0 + 8) * ASTR + kcol];
                Ah[mi][0] = __float_as_uint(h0.x); Ah[mi][2] = __float_as_uint(h0.y);
                Ah[mi][1] = __float_as_uint(h1.x); Ah[mi][3] = __float_as_uint(h1.y);
                Al[mi][0] = __float_as_uint(l0.x); Al[mi][2] = __float_as_uint(l0.y);
                Al[mi][1] = __float_as_uint(l1.x); Al[mi][3] = __float_as_uint(l1.y);
            }
#pragma unroll
            for (int ni = 0; ni < 8; ni++) {
                int rn = wn + ni * 8 + g;
                float2 h = *(const float2*)&sBh[rn * ASTR + kcol];
                float2 l = *(const float2*)&sBl[rn * ASTR + kcol];
                uint32_t Bh[2], Bl[2];
                Bh[0] = __float_as_uint(h.x); Bh[1] = __float_as_uint(h.y);
                Bl[0] = __float_as_uint(l.x); Bl[1] = __float_as_uint(l.y);
#pragma unroll
                for (int mi = 0; mi < 2; mi++) {
                    mma1688(acc[mi][ni], Ah[mi], Bh);
                    mma1688(acc[mi][ni], Ah[mi], Bl);
                    mma1688(acc[mi][ni], Al[mi], Bh);
                }
            }
        }
        __syncthreads();
        if (i + 2 < NCHUNK) load_chunk(i + 2, s);
    }

    // ---- epilogue: +bias, logsig, float2 stores to table[v][c] ----
#pragma unroll
    for (int ni = 0; ni < 8; ni++) {
        const int c = cBase + wn + ni * 8 + 2 * t;
        if (c >= CDIM) continue;
        const float b0 = __ldg(&bias[(c / 5) * 6 + (c % 5)]);
        const int c1 = c + 1;
        const float b1 = __ldg(&bias[(c1 / 5) * 6 + (c1 % 5)]);
#pragma unroll
        for (int mi = 0; mi < 2; mi++) {
            const int v0 = vBase + wm + mi * 16 + g;
            const int v1 = v0 + 8;
            if (v0 < VDIM) {
                float2 r;
                r.x = logsig(acc[mi][ni][0] + b0);
                r.y = logsig(acc[mi][ni][1] + b1);
                *(float2*)&d_table[(size_t)v0 * TSTR + c] = r;
            }
            if (v1 < VDIM) {
                float2 r;
                r.x = logsig(acc[mi][ni][2] + b0);
                r.y = logsig(acc[mi][ni][3] + b1);
                *(float2*)&d_table[(size_t)v1 * TSTR + c] = r;
            }
        }
    }
}

// ---------------------------------------------------------------------------
// 4. chunked scan: block (b, ch) covers positions [ch*32, ch*32+32) with a
//    4-token warmup (hid state is a sliding-window sum of depth <= 5).
// ---------------------------------------------------------------------------
__global__ void __launch_bounds__(160)
scan_part_kernel(const int*   __restrict__ docs,
                 const int*   __restrict__ doc_lens,
                 const float* __restrict__ wildcards) {
    const int b   = blockIdx.x;
    const int ch  = blockIdx.y;
    const int tid = threadIdx.x;
    const int p   = tid;
    const bool valid = (p < PDIM);

    const int len = doc_lens[b];
    const int c0  = ch * SCT;
    if (len <= c0) {
        if (valid) d_part[b][ch][p] = NEGF;
        return;
    }

    const int warm   = (ch == 0) ? 0 : 4;
    const int tstart = c0 - warm;
    const int nt     = warm + SCT;   // 32 or 36 (both %4 == 0)

    __shared__ int s_tok[SCT + 4];
    for (int i = tid; i < nt; i += 160) s_tok[i] = docs[b * LDIM + tstart + i];
    __syncthreads();

    float wl[5];
#pragma unroll
    for (int m = 0; m < 5; m++)
        wl[m] = valid ? logsig(__ldg(&wildcards[p * 5 + m])) : 0.0f;

    const int endSel = p / 50;
    float h1 = NEGF, h2 = NEGF, h3 = NEGF, h4 = NEGF, h5 = NEGF;
    float sc = NEGF;

    float pf[4][5];
#pragma unroll
    for (int u = 0; u < 4; u++) {
        if (valid && u < nt) {
            const float* row = &d_table[(size_t)s_tok[u] * TSTR + p * 5];
#pragma unroll
            for (int m = 0; m < 5; m++) pf[u][m] = __ldg(&row[m]);
        } else {
#pragma unroll
            for (int m = 0; m < 5; m++) pf[u][m] = 0.0f;
        }
    }

    const int scoreLo = warm;
    const int scoreHi = (len < c0 + SCT ? len : c0 + SCT) - tstart;

    for (int i = 0; i < nt; i += 4) {
#pragma unroll
        for (int u = 0; u < 4; u++) {
            float e0 = fmaxf(pf[u][0], wl[0]);
            float e1 = fmaxf(pf[u][1], wl[1]);
            float e2 = fmaxf(pf[u][2], wl[2]);
            float e3 = fmaxf(pf[u][3], wl[3]);
            float e4 = fmaxf(pf[u][4], wl[4]);
            h5 = h4 + e4;
            h4 = h3 + e3;
            h3 = h2 + e2;
            h2 = h1 + e1;
            h1 = e0;
            float ev = (endSel == 0) ? h3 : ((endSel == 1) ? h4 : h5);
            int li = i + u;
            sc = (li >= scoreLo && li < scoreHi) ? fmaxf(sc, ev) : sc;
            int ni = li + 4;
            if (ni < nt && valid) {
                const float* row = &d_table[(size_t)s_tok[ni] * TSTR + p * 5];
#pragma unroll
                for (int m = 0; m < 5; m++) pf[u][m] = __ldg(&row[m]);
            }
        }
    }

    if (valid) d_part[b][ch][p] = sc;
}

// ---------------------------------------------------------------------------
// 5. final: reduce chunks, exp/LN/heaviside/linear
// ---------------------------------------------------------------------------
__global__ void __launch_bounds__(160)
scan_final_kernel(const float* __restrict__ gamma,
                  const float* __restrict__ beta,
                  const float* __restrict__ W,
                  const float* __restrict__ lb,
                  float*       __restrict__ out) {
    const int b   = blockIdx.x;
    const int tid = threadIdx.x;
    const bool valid = (tid < PDIM);

    __shared__ float sh[192];
    __shared__ float sred[2];

    float sc = NEGF;
    if (valid) {
#pragma unroll
        for (int ch = 0; ch < NSC; ch++) sc = fmaxf(sc, d_part[b][ch][tid]);
    }
    float score = valid ? expf(sc) : 0.0f;

    sh[tid] = score;
    __syncthreads();
    if (tid < 32) {
        float s = 0.0f;
        for (int i = tid; i < PDIM; i += 32) s += sh[i];
#pragma unroll
        for (int o = 16; o > 0; o >>= 1) s += __shfl_down_sync(0xffffffffu, s, o);
        if (tid == 0) sred[0] = s * (1.0f / PDIM);
    }
    __syncthreads();
    const float mu = sred[0];

    float d = score - mu;
    sh[tid] = valid ? d * d : 0.0f;
    __syncthreads();
    if (tid < 32) {
        float s = 0.0f;
        for (int i = tid; i < PDIM; i += 32) s += sh[i];
#pragma unroll
        for (int o = 16; o > 0; o >>= 1) s += __shfl_down_sync(0xffffffffu, s, o);
        if (tid == 0) sred[1] = s * (1.0f / PDIM);
    }
    __syncthreads();
    const float var = sred[1];

    float bin = 0.0f;
    if (valid) {
        float norm = (score - mu) * rsqrtf(var + 1e-5f) * __ldg(&gamma[tid]) + __ldg(&beta[tid]);
        bin = (norm > 0.0f) ? 1.0f : 0.0f;
    }

    sh[tid] = valid ? bin * __ldg(&W[tid]) : 0.0f;
    __syncthreads();
    if (tid < 32) {
        float s = 0.0f;
        for (int i = tid; i < PDIM; i += 32) s += sh[i];
#pragma unroll
        for (int o = 16; o > 0; o >>= 1) s += __shfl_down_sync(0xffffffffu, s, o);
        if (tid == 0) out[b * 2 + 0] = s + __ldg(&lb[0]);
    }
    __syncthreads();
    sh[tid] = valid ? bin * __ldg(&W[PDIM + tid]) : 0.0f;
    __syncthreads();
    if (tid < 32) {
        float s = 0.0f;
        for (int i = tid; i < PDIM; i += 32) s += sh[i];
#pragma unroll
        for (int o = 16; o > 0; o >>= 1) s += __shfl_down_sync(0xffffffffu, s, o);
        if (tid == 0) out[b * 2 + 1] = s + __ldg(&lb[1]);
    }
}

// ---------------------------------------------------------------------------
// launch
// ---------------------------------------------------------------------------
extern "C" void kernel_launch(void* const* d_in, const int* in_sizes, int n_in,
                              void* d_out, int out_size) {
    const int*   docs      = (const int*)  d_in[0];
    const int*   doc_lens  = (const int*)  d_in[1];
    const float* emb       = (const float*)d_in[2];
    const float* diags     = (const float*)d_in[3];
    const float* bias      = (const float*)d_in[4];
    const float* wildcards = (const float*)d_in[5];
    const float* ln_gamma  = (const float*)d_in[6];
    const float* ln_beta   = (const float*)d_in[7];
    const float* linear_w  = (const float*)d_in[8];
    const float* linear_b  = (const float*)d_in[9];
    float*       out       = (float*)d_out;

    (void)in_sizes; (void)n_in; (void)out_size;

    cudaFuncSetAttribute(gemm_mma_kernel,
                         cudaFuncAttributeMaxDynamicSharedMemorySize, GSMEM_TOTAL);

    split_diags_kernel<<<(CPAD * KPAD + 255) / 256, 256>>>(diags);

    dim3 tgrid(VPAD / 32, (KPAD + 31) / 32);  // (632, 10)
    split_emb_kernel<<<tgrid, dim3(32, 8)>>>(emb);

    dim3 ggrid(VPAD / 128, CPAD / 128);       // (158, 6)
    gemm_mma_kernel<<<ggrid, 256, GSMEM_TOTAL>>>(bias);

    dim3 sgrid(BDIM, NSC);                    // (64, 16)
    scan_part_kernel<<<sgrid, 160>>>(docs, doc_lens, wildcards);

    scan_final_kernel<<<BDIM, 160>>>(ln_gamma, ln_beta, linear_w, linear_b, out);
}

// round 8
// speedup vs baseline: 2.2818x; 1.5748x over previous
#include <cuda_runtime.h>
#include <cuda_fp16.h>
#include <cstdint>

// ---------------------------------------------------------------------------
// SoftPatternClassifier on GB300 — mma.sync 3xFP16-split GEMM + chunked scan
//   R8: m16n8k16 f16 (2048 MAC/instr) replaces tf32 k8 -> half the MMA instrs.
// ---------------------------------------------------------------------------

#define BDIM 64
#define LDIM 512
#define VDIM 20000
#define PDIM 150
#define CDIM 750
#define KDIM 300
#define NEGF (-1000000000.0f)

#define TSTR 752
#define KPAD 320              // 10 chunks of 32
#define NPAIR (KPAD / 2)      // 160 half2 pairs per row
#define CPAD 768
#define VPAD 20224            // 158 * 128

#define TK 32                 // K values per chunk (16 pairs)
#define NCHUNK (KPAD / TK)    // 10
#define ASTR 24               // smem row stride (floats); payload 16 floats

#define NSC 16                // scan time-chunks
#define SCT 32                // positions per scan chunk

// __device__ scratch (allocation-free rule)
__device__ float   d_table[(size_t)VDIM * TSTR];  // ~60 MB
__device__ __half2 d_Ahi[CPAD * NPAIR];
__device__ __half2 d_Alo[CPAD * NPAIR];
__device__ __half2 d_Bhi[(size_t)VPAD * NPAIR];   // ~6.5 MB
__device__ __half2 d_Blo[(size_t)VPAD * NPAIR];   // ~6.5 MB
__device__ float   d_part[BDIM][NSC][160];

// ---------------------------------------------------------------------------
// helpers
// ---------------------------------------------------------------------------
__device__ __forceinline__ float logsig(float x) {
    return fminf(x, 0.0f) - log1pf(expf(-fabsf(x)));
}
__device__ __forceinline__ void cpa16(uint32_t dst, const void* src) {
    asm volatile("cp.async.cg.shared.global [%0], [%1], 16;" :: "r"(dst), "l"(src) : "memory");
}
#define CPA_COMMIT() asm volatile("cp.async.commit_group;" ::: "memory")
#define CPA_WAIT1()  asm volatile("cp.async.wait_group 1;" ::: "memory")
#define CPA_WAIT0()  asm volatile("cp.async.wait_group 0;" ::: "memory")

__device__ __forceinline__ uint32_t smem_u32(const void* p) {
    uint32_t a;
    asm("{ .reg .u64 t; cvta.to.shared.u64 t, %1; cvt.u32.u64 %0, t; }" : "=r"(a) : "l"(p));
    return a;
}

// pair-interleave within groups of 8 pairs: stored order (0,4,1,5,2,6,3,7)
__device__ __forceinline__ int pslot(int j) {
    return (j & ~7) + 2 * (j & 3) + ((j >> 2) & 1);
}

// m16n8k16 fp16 inputs, fp32 accumulate
__device__ __forceinline__ void mma16816(float* d, uint32_t a0, uint32_t a1,
                                         uint32_t a2, uint32_t a3,
                                         uint32_t b0, uint32_t b1) {
    asm volatile(
        "mma.sync.aligned.m16n8k16.row.col.f32.f16.f16.f32 "
        "{%0,%1,%2,%3}, {%4,%5,%6,%7}, {%8,%9}, {%0,%1,%2,%3};"
        : "+f"(d[0]), "+f"(d[1]), "+f"(d[2]), "+f"(d[3])
        : "r"(a0), "r"(a1), "r"(a2), "r"(a3), "r"(b0), "r"(b1));
}

__device__ __forceinline__ void fp16split(float x, __half& h, __half& l) {
    h = __float2half_rn(x);
    l = __float2half_rn(x - __half2float(h));
}

// ---------------------------------------------------------------------------
// 1. split diags -> fp16 hi/lo half2 pairs, [CPAD][NPAIR], pair-interleaved
// ---------------------------------------------------------------------------
__global__ void split_diags_kernel(const float* __restrict__ diags) {
    int i = blockIdx.x * blockDim.x + threadIdx.x;
    if (i >= CPAD * NPAIR) return;
    int c = i / NPAIR;
    int j = i - c * NPAIR;
    int k0 = 2 * j, k1 = 2 * j + 1;
    float x0 = 0.0f, x1 = 0.0f;
    if (c < CDIM) {
        int row = (c / 5) * 6 + (c % 5);
        if (k0 < KDIM) x0 = diags[row * KDIM + k0];
        if (k1 < KDIM) x1 = diags[row * KDIM + k1];
    }
    __half h0, l0, h1, l1;
    fp16split(x0, h0, l0);
    fp16split(x1, h1, l1);
    int dst = c * NPAIR + pslot(j);
    d_Ahi[dst] = __halves2half2(h0, h1);
    d_Alo[dst] = __halves2half2(l0, l1);
}

// ---------------------------------------------------------------------------
// 2. transpose+split E [300][20000] -> B_hi/B_lo [VPAD][NPAIR] half2 pairs
// ---------------------------------------------------------------------------
__global__ void split_emb_kernel(const float* __restrict__ E) {
    __shared__ float tile[32][33];
    int vt = blockIdx.x * 32;
    int kt = blockIdx.y * 32;
    int tx = threadIdx.x, ty = threadIdx.y;   // (32, 8)
#pragma unroll
    for (int r = 0; r < 4; r++) {
        int k = kt + ty + r * 8, v = vt + tx;
        tile[ty + r * 8][tx] = (k < KDIM && v < VDIM) ? E[(size_t)k * VDIM + v] : 0.0f;
    }
    __syncthreads();
    int tid = ty * 32 + tx;
#pragma unroll
    for (int w = 0; w < 2; w++) {
        int idx = tid + 256 * w;               // 0..511 = 32 v x 16 pairs
        int j = idx & 15, vv = idx >> 4;
        float x0 = tile[2 * j][vv];
        float x1 = tile[2 * j + 1][vv];
        __half h0, l0, h1, l1;
        fp16split(x0, h0, l0);
        fp16split(x1, h1, l1);
        int gp = (kt >> 1) + j;                // global pair index
        size_t o = (size_t)(vt + vv) * NPAIR + pslot(gp);
        d_Bhi[o] = __halves2half2(h0, h1);
        d_Blo[o] = __halves2half2(l0, l1);
    }
}

// ---------------------------------------------------------------------------
// 3. GEMM via mma.sync m16n8k16 f16, 3x split.
//    CTA: 128 v x 128 c, 256 thr (8 warps, 4(m) x 2(n), warp = 32v x 64c).
//    K: 10 chunks of 32, double-buffered cp.async, 2 CTAs/SM.
// ---------------------------------------------------------------------------
#define ARR_BYTES  (128 * ASTR * 4)            // 12288
#define STAGE_BYTES (4 * ARR_BYTES)            // 49152
#define GSMEM_TOTAL (2 * STAGE_BYTES)          // 98304
#define OFF_AH 0
#define OFF_AL ARR_BYTES
#define OFF_BH (2 * ARR_BYTES)
#define OFF_BL (3 * ARR_BYTES)

__global__ void __launch_bounds__(256, 2)
gemm_mma_kernel(const float* __restrict__ bias) {
    extern __shared__ __align__(16) char smem[];
    const uint32_t sb = smem_u32(smem);

    const int tid = threadIdx.x;
    const int wid = tid >> 5;
    const int lid = tid & 31;
    const int g   = lid >> 2;       // 0..7
    const int t   = lid & 3;        // 0..3
    const int wm  = (wid & 3) * 32;
    const int wn  = (wid >> 2) * 64;

    const int vBase = blockIdx.x * 128;
    const int cBase = blockIdx.y * 128;

    const __half2* gBh = d_Bhi + (size_t)vBase * NPAIR;   // MMA A operand (m = v)
    const __half2* gBl = d_Blo + (size_t)vBase * NPAIR;
    const __half2* gAh = d_Ahi + (size_t)cBase * NPAIR;   // MMA B operand (n = c)
    const __half2* gAl = d_Alo + (size_t)cBase * NPAIR;

    auto load_chunk = [&](int kc, int s) {
        const uint32_t st = sb + s * STAGE_BYTES;
        const int p0 = kc * 16;                 // first pair of chunk
#pragma unroll
        for (int it = 0; it < 2; it++) {
            int idx = tid + it * 256;           // 0..511
            int r = idx >> 2, q = (idx & 3) * 4;            // 4 half2 = 16B
            uint32_t so = (uint32_t)(r * ASTR + q) * 4;
            size_t go = (size_t)r * NPAIR + p0 + q;
            cpa16(st + OFF_AH + so, gBh + go);
            cpa16(st + OFF_AL + so, gBl + go);
            cpa16(st + OFF_BH + so, gAh + go);
            cpa16(st + OFF_BL + so, gAl + go);
        }
        CPA_COMMIT();
    };

    float acc[2][8][4];
#pragma unroll
    for (int mi = 0; mi < 2; mi++)
#pragma unroll
        for (int ni = 0; ni < 8; ni++)
#pragma unroll
            for (int e = 0; e < 4; e++) acc[mi][ni][e] = 0.0f;

    load_chunk(0, 0);
    load_chunk(1, 1);

    for (int i = 0; i < NCHUNK; i++) {
        const int s = i & 1;
        if (i + 1 < NCHUNK) { CPA_WAIT1(); } else { CPA_WAIT0(); }
        __syncthreads();

        const float* sAh = (const float*)(smem + s * STAGE_BYTES + OFF_AH);
        const float* sAl = (const float*)(smem + s * STAGE_BYTES + OFF_AL);
        const float* sBh = (const float*)(smem + s * STAGE_BYTES + OFF_BH);
        const float* sBl = (const float*)(smem + s * STAGE_BYTES + OFF_BL);

#pragma unroll
        for (int ks = 0; ks < 2; ks++) {        // two k16 groups per chunk
            const int kcol = ks * 8 + 2 * t;    // float (= pair-slot) offset

            // A fragments (v rows): a0=f0.x a1=f1.x a2=f0.y a3=f1.y
            uint32_t Ah[2][4], Al[2][4];
#pragma unroll
            for (int mi = 0; mi < 2; mi++) {
                int r0 = wm + mi * 16 + g;
                float2 h0 = *(const float2*)&sAh[r0 * ASTR + kcol];
                float2 h1 = *(const float2*)&sAh[(r0 + 8) * ASTR + kcol];
                float2 l0 = *(const float2*)&sAl[r0 * ASTR + kcol];
                float2 l1 = *(const float2*)&sAl[(r0 + 8) * ASTR + kcol];
                Ah[mi][0] = __float_as_uint(h0.x); Ah[mi][1] = __float_as_uint(h1.x);
                Ah[mi][2] = __float_as_uint(h0.y); Ah[mi][3] = __float_as_uint(h1.y);
                Al[mi][0] = __float_as_uint(l0.x); Al[mi][1] = __float_as_uint(l1.x);
                Al[mi][2] = __float_as_uint(l0.y); Al[mi][3] = __float_as_uint(l1.y);
            }
#pragma unroll
            for (int ni = 0; ni < 8; ni++) {
                int rn = wn + ni * 8 + g;
                float2 h = *(const float2*)&sBh[rn * ASTR + kcol];
                float2 l = *(const float2*)&sBl[rn * ASTR + kcol];
                uint32_t bh0 = __float_as_uint(h.x), bh1 = __float_as_uint(h.y);
                uint32_t bl0 = __float_as_uint(l.x), bl1 = __float_as_uint(l.y);
#pragma unroll
                for (int mi = 0; mi < 2; mi++) {
                    mma16816(acc[mi][ni], Ah[mi][0], Ah[mi][1], Ah[mi][2], Ah[mi][3], bh0, bh1);
                    mma16816(acc[mi][ni], Ah[mi][0], Ah[mi][1], Ah[mi][2], Ah[mi][3], bl0, bl1);
                    mma16816(acc[mi][ni], Al[mi][0], Al[mi][1], Al[mi][2], Al[mi][3], bh0, bh1);
                }
            }
        }
        __syncthreads();
        if (i + 2 < NCHUNK) load_chunk(i + 2, s);
    }

    // ---- epilogue: +bias, logsig, float2 stores to table[v][c] ----
#pragma unroll
    for (int ni = 0; ni < 8; ni++) {
        const int c = cBase + wn + ni * 8 + 2 * t;
        if (c >= CDIM) continue;
        const float b0 = __ldg(&bias[(c / 5) * 6 + (c % 5)]);
        const int c1 = c + 1;
        const float b1 = __ldg(&bias[(c1 / 5) * 6 + (c1 % 5)]);
#pragma unroll
        for (int mi = 0; mi < 2; mi++) {
            const int v0 = vBase + wm + mi * 16 + g;
            const int v1 = v0 + 8;
            if (v0 < VDIM) {
                float2 r;
                r.x = logsig(acc[mi][ni][0] + b0);
                r.y = logsig(acc[mi][ni][1] + b1);
                *(float2*)&d_table[(size_t)v0 * TSTR + c] = r;
            }
            if (v1 < VDIM) {
                float2 r;
                r.x = logsig(acc[mi][ni][2] + b0);
                r.y = logsig(acc[mi][ni][3] + b1);
                *(float2*)&d_table[(size_t)v1 * TSTR + c] = r;
            }
        }
    }
}

// ---------------------------------------------------------------------------
// 4. chunked scan: block (b, ch) covers positions [ch*32, ch*32+32) with a
//    4-token warmup (hid state is a sliding-window sum of depth <= 5).
// ---------------------------------------------------------------------------
__global__ void __launch_bounds__(160)
scan_part_kernel(const int*   __restrict__ docs,
                 const int*   __restrict__ doc_lens,
                 const float* __restrict__ wildcards) {
    const int b   = blockIdx.x;
    const int ch  = blockIdx.y;
    const int tid = threadIdx.x;
    const int p   = tid;
    const bool valid = (p < PDIM);

    const int len = doc_lens[b];
    const int c0  = ch * SCT;
    if (len <= c0) {
        if (valid) d_part[b][ch][p] = NEGF;
        return;
    }

    const int warm   = (ch == 0) ? 0 : 4;
    const int tstart = c0 - warm;
    const int nt     = warm + SCT;   // 32 or 36

    __shared__ int s_tok[SCT + 4];
    for (int i = tid; i < nt; i += 160) s_tok[i] = docs[b * LDIM + tstart + i];
    __syncthreads();

    float wl[5];
#pragma unroll
    for (int m = 0; m < 5; m++)
        wl[m] = valid ? logsig(__ldg(&wildcards[p * 5 + m])) : 0.0f;

    const int endSel = p / 50;
    float h1 = NEGF, h2 = NEGF, h3 = NEGF, h4 = NEGF, h5 = NEGF;
    float sc = NEGF;

    float pf[4][5];
#pragma unroll
    for (int u = 0; u < 4; u++) {
        if (valid && u < nt) {
            const float* row = &d_table[(size_t)s_tok[u] * TSTR + p * 5];
#pragma unroll
            for (int m = 0; m < 5; m++) pf[u][m] = __ldg(&row[m]);
        } else {
#pragma unroll
            for (int m = 0; m < 5; m++) pf[u][m] = 0.0f;
        }
    }

    const int scoreLo = warm;
    const int scoreHi = (len < c0 + SCT ? len : c0 + SCT) - tstart;

    for (int i = 0; i < nt; i += 4) {
#pragma unroll
        for (int u = 0; u < 4; u++) {
            float e0 = fmaxf(pf[u][0], wl[0]);
            float e1 = fmaxf(pf[u][1], wl[1]);
            float e2 = fmaxf(pf[u][2], wl[2]);
            float e3 = fmaxf(pf[u][3], wl[3]);
            float e4 = fmaxf(pf[u][4], wl[4]);
            h5 = h4 + e4;
            h4 = h3 + e3;
            h3 = h2 + e2;
            h2 = h1 + e1;
            h1 = e0;
            float ev = (endSel == 0) ? h3 : ((endSel == 1) ? h4 : h5);
            int li = i + u;
            sc = (li >= scoreLo && li < scoreHi) ? fmaxf(sc, ev) : sc;
            int ni = li + 4;
            if (ni < nt && valid) {
                const float* row = &d_table[(size_t)s_tok[ni] * TSTR + p * 5];
#pragma unroll
                for (int m = 0; m < 5; m++) pf[u][m] = __ldg(&row[m]);
            }
        }
    }

    if (valid) d_part[b][ch][p] = sc;
}

// ---------------------------------------------------------------------------
// 5. final: reduce chunks, exp/LN/heaviside/linear
// ---------------------------------------------------------------------------
__global__ void __launch_bounds__(160)
scan_final_kernel(const float* __restrict__ gamma,
                  const float* __restrict__ beta,
                  const float* __restrict__ W,
                  const float* __restrict__ lb,
                  float*       __restrict__ out) {
    const int b   = blockIdx.x;
    const int tid = threadIdx.x;
    const bool valid = (tid < PDIM);

    __shared__ float sh[192];
    __shared__ float sred[2];

    float sc = NEGF;
    if (valid) {
#pragma unroll
        for (int ch = 0; ch < NSC; ch++) sc = fmaxf(sc, d_part[b][ch][tid]);
    }
    float score = valid ? expf(sc) : 0.0f;

    sh[tid] = score;
    __syncthreads();
    if (tid < 32) {
        float s = 0.0f;
        for (int i = tid; i < PDIM; i += 32) s += sh[i];
#pragma unroll
        for (int o = 16; o > 0; o >>= 1) s += __shfl_down_sync(0xffffffffu, s, o);
        if (tid == 0) sred[0] = s * (1.0f / PDIM);
    }
    __syncthreads();
    const float mu = sred[0];

    float d = score - mu;
    sh[tid] = valid ? d * d : 0.0f;
    __syncthreads();
    if (tid < 32) {
        float s = 0.0f;
        for (int i = tid; i < PDIM; i += 32) s += sh[i];
#pragma unroll
        for (int o = 16; o > 0; o >>= 1) s += __shfl_down_sync(0xffffffffu, s, o);
        if (tid == 0) sred[1] = s * (1.0f / PDIM);
    }
    __syncthreads();
    const float var = sred[1];

    float bin = 0.0f;
    if (valid) {
        float norm = (score - mu) * rsqrtf(var + 1e-5f) * __ldg(&gamma[tid]) + __ldg(&beta[tid]);
        bin = (norm > 0.0f) ? 1.0f : 0.0f;
    }

    sh[tid] = valid ? bin * __ldg(&W[tid]) : 0.0f;
    __syncthreads();
    if (tid < 32) {
        float s = 0.0f;
        for (int i = tid; i < PDIM; i += 32) s += sh[i];
#pragma unroll
        for (int o = 16; o > 0; o >>= 1) s += __shfl_down_sync(0xffffffffu, s, o);
        if (tid == 0) out[b * 2 + 0] = s + __ldg(&lb[0]);
    }
    __syncthreads();
    sh[tid] = valid ? bin * __ldg(&W[PDIM + tid]) : 0.0f;
    __syncthreads();
    if (tid < 32) {
        float s = 0.0f;
        for (int i = tid; i < PDIM; i += 32) s += sh[i];
#pragma unroll
        for (int o = 16; o > 0; o >>= 1) s += __shfl_down_sync(0xffffffffu, s, o);
        if (tid == 0) out[b * 2 + 1] = s + __ldg(&lb[1]);
    }
}

// ---------------------------------------------------------------------------
// launch
// ---------------------------------------------------------------------------
extern "C" void kernel_launch(void* const* d_in, const int* in_sizes, int n_in,
                              void* d_out, int out_size) {
    const int*   docs      = (const int*)  d_in[0];
    const int*   doc_lens  = (const int*)  d_in[1];
    const float* emb       = (const float*)d_in[2];
    const float* diags     = (const float*)d_in[3];
    const float* bias      = (const float*)d_in[4];
    const float* wildcards = (const float*)d_in[5];
    const float* ln_gamma  = (const float*)d_in[6];
    const float* ln_beta   = (const float*)d_in[7];
    const float* linear_w  = (const float*)d_in[8];
    const float* linear_b  = (const float*)d_in[9];
    float*       out       = (float*)d_out;

    (void)in_sizes; (void)n_in; (void)out_size;

    cudaFuncSetAttribute(gemm_mma_kernel,
                         cudaFuncAttributeMaxDynamicSharedMemorySize, GSMEM_TOTAL);

    split_diags_kernel<<<(CPAD * NPAIR + 255) / 256, 256>>>(diags);

    dim3 tgrid(VPAD / 32, KPAD / 32);         // (632, 10)
    split_emb_kernel<<<tgrid, dim3(32, 8)>>>(emb);

    dim3 ggrid(VPAD / 128, CPAD / 128);       // (158, 6)
    gemm_mma_kernel<<<ggrid, 256, GSMEM_TOTAL>>>(bias);

    dim3 sgrid(BDIM, NSC);                    // (64, 16)
    scan_part_kernel<<<sgrid, 160>>>(docs, doc_lens, wildcards);

    scan_final_kernel<<<BDIM, 160>>>(ln_gamma, ln_beta, linear_w, linear_b, out);
}

// round 9
// speedup vs baseline: 3.0434x; 1.3338x over previous
#include <cuda_runtime.h>
#include <cuda_fp16.h>
#include <cstdint>

// ---------------------------------------------------------------------------
// SoftPatternClassifier on GB300 — vocab-compacted 3xFP16 mma.sync GEMM
//   R9: GEMM only over tokens actually present in docs (within doc_lens):
//       expected ~11.2K of 20000 rows  -> ~44% less tensor work.
//       KPAD 320->304 (19 k16 chunks)  -> 5% fewer MMA instructions.
// ---------------------------------------------------------------------------

#define BDIM 64
#define LDIM 512
#define VDIM 20000
#define PDIM 150
#define CDIM 750
#define KDIM 300
#define NEGF (-1000000000.0f)

#define TSTR 752
#define KPAD 304              // 19 chunks of 16
#define NPAIR (KPAD / 2)      // 152 half2 pairs per row
#define CPAD 768
#define VPAD 20096            // 157 * 128

#define TK 16                 // K values per chunk (8 pairs)
#define NCHUNK (KPAD / TK)    // 19
#define ASTR 12               // smem row stride (floats); payload 8

#define NSC 16                // scan time-chunks
#define SCT 32                // positions per scan chunk

// __device__ scratch (allocation-free rule)
__device__ float   d_table[(size_t)VPAD * TSTR];  // ~60 MB (cid-indexed)
__device__ __half2 d_Ahi[CPAD * NPAIR];
__device__ __half2 d_Alo[CPAD * NPAIR];
__device__ __half2 d_Bhi[(size_t)VPAD * NPAIR];   // ~6.1 MB (token-indexed)
__device__ __half2 d_Blo[(size_t)VPAD * NPAIR];
__device__ float   d_part[BDIM][NSC][160];
__device__ int     d_flag[VDIM];
__device__ int     d_cid[VDIM];                   // token -> compact id (0 if unused)
__device__ int     d_used[VPAD];                  // compact id -> token
__device__ int     d_count;

// ---------------------------------------------------------------------------
// helpers
// ---------------------------------------------------------------------------
__device__ __forceinline__ float logsig(float x) {
    return fminf(x, 0.0f) - log1pf(expf(-fabsf(x)));
}
__device__ __forceinline__ void cpa16(uint32_t dst, const void* src) {
    asm volatile("cp.async.cg.shared.global [%0], [%1], 16;" :: "r"(dst), "l"(src) : "memory");
}
#define CPA_COMMIT() asm volatile("cp.async.commit_group;" ::: "memory")
#define CPA_WAIT1()  asm volatile("cp.async.wait_group 1;" ::: "memory")
#define CPA_WAIT0()  asm volatile("cp.async.wait_group 0;" ::: "memory")

__device__ __forceinline__ uint32_t smem_u32(const void* p) {
    uint32_t a;
    asm("{ .reg .u64 t; cvta.to.shared.u64 t, %1; cvt.u32.u64 %0, t; }" : "=r"(a) : "l"(p));
    return a;
}

// pair-interleave within groups of 8 pairs: stored order (0,4,1,5,2,6,3,7)
__device__ __forceinline__ int pslot(int j) {
    return (j & ~7) + 2 * (j & 3) + ((j >> 2) & 1);
}

__device__ __forceinline__ void mma16816(float* d, uint32_t a0, uint32_t a1,
                                         uint32_t a2, uint32_t a3,
                                         uint32_t b0, uint32_t b1) {
    asm volatile(
        "mma.sync.aligned.m16n8k16.row.col.f32.f16.f16.f32 "
        "{%0,%1,%2,%3}, {%4,%5,%6,%7}, {%8,%9}, {%0,%1,%2,%3};"
        : "+f"(d[0]), "+f"(d[1]), "+f"(d[2]), "+f"(d[3])
        : "r"(a0), "r"(a1), "r"(a2), "r"(a3), "r"(b0), "r"(b1));
}

__device__ __forceinline__ void fp16split(float x, __half& h, __half& l) {
    h = __float2half_rn(x);
    l = __float2half_rn(x - __half2float(h));
}

// ---------------------------------------------------------------------------
// 0a. clear flags / maps / count
// ---------------------------------------------------------------------------
__global__ void clear_kernel() {
    int i = blockIdx.x * blockDim.x + threadIdx.x;
    if (i < VDIM) { d_flag[i] = 0; d_cid[i] = 0; }
    if (i < VPAD) d_used[i] = 0;
    if (i == 0) d_count = 0;
}

// 0b. mark tokens appearing within doc_lens
__global__ void mark_kernel(const int* __restrict__ docs,
                            const int* __restrict__ doc_lens) {
    int i = blockIdx.x * blockDim.x + threadIdx.x;     // over B*L
    int b = i >> 9, t = i & (LDIM - 1);
    if (b < BDIM && t < doc_lens[b]) d_flag[docs[i]] = 1;
}

// 0c. assign compact ids (warp-aggregated atomics; VDIM = 625 full warps)
__global__ void assign_kernel() {
    int v = blockIdx.x * blockDim.x + threadIdx.x;
    if (v >= VDIM) return;
    int lane = threadIdx.x & 31;
    int f = d_flag[v];
    unsigned mask = __ballot_sync(0xffffffffu, f != 0);
    int base = 0;
    if (lane == 0 && mask) base = atomicAdd(&d_count, __popc(mask));
    base = __shfl_sync(0xffffffffu, base, 0);
    if (f) {
        int cid = base + __popc(mask & ((1u << lane) - 1));
        d_cid[v] = cid;
        d_used[cid] = v;
    }
}

// ---------------------------------------------------------------------------
// 1. split diags -> fp16 hi/lo half2 pairs, [CPAD][NPAIR], pair-interleaved
// ---------------------------------------------------------------------------
__global__ void split_diags_kernel(const float* __restrict__ diags) {
    int i = blockIdx.x * blockDim.x + threadIdx.x;
    if (i >= CPAD * NPAIR) return;
    int c = i / NPAIR;
    int j = i - c * NPAIR;
    int k0 = 2 * j, k1 = 2 * j + 1;
    float x0 = 0.0f, x1 = 0.0f;
    if (c < CDIM) {
        int row = (c / 5) * 6 + (c % 5);
        if (k0 < KDIM) x0 = diags[row * KDIM + k0];
        if (k1 < KDIM) x1 = diags[row * KDIM + k1];
    }
    __half h0, l0, h1, l1;
    fp16split(x0, h0, l0);
    fp16split(x1, h1, l1);
    int dst = c * NPAIR + pslot(j);
    d_Ahi[dst] = __halves2half2(h0, h1);
    d_Alo[dst] = __halves2half2(l0, l1);
}

// ---------------------------------------------------------------------------
// 2. transpose+split E [300][20000] -> B_hi/B_lo [VPAD][NPAIR] (token rows)
// ---------------------------------------------------------------------------
__global__ void split_emb_kernel(const float* __restrict__ E) {
    __shared__ float tile[32][33];
    int vt = blockIdx.x * 32;
    int kt = blockIdx.y * 32;
    int tx = threadIdx.x, ty = threadIdx.y;   // (32, 8)
#pragma unroll
    for (int r = 0; r < 4; r++) {
        int k = kt + ty + r * 8, v = vt + tx;
        tile[ty + r * 8][tx] = (k < KDIM && v < VDIM) ? E[(size_t)k * VDIM + v] : 0.0f;
    }
    __syncthreads();
    int tid = ty * 32 + tx;
#pragma unroll
    for (int w = 0; w < 2; w++) {
        int idx = tid + 256 * w;               // 0..511 = 32 v x 16 pairs
        int j = idx & 15, vv = idx >> 4;
        int gp = (kt >> 1) + j;                // global pair index
        if (gp >= NPAIR) continue;
        float x0 = tile[2 * j][vv];
        float x1 = tile[2 * j + 1][vv];
        __half h0, l0, h1, l1;
        fp16split(x0, h0, l0);
        fp16split(x1, h1, l1);
        size_t o = (size_t)(vt + vv) * NPAIR + pslot(gp);
        d_Bhi[o] = __halves2half2(h0, h1);
        d_Blo[o] = __halves2half2(l0, l1);
    }
}

// ---------------------------------------------------------------------------
// 3. GEMM over USED tokens only: D[128 cid x 128 c] per CTA.
//    mma.sync m16n8k16 f16, 3x split; 19 k16 chunks, double-buffered.
// ---------------------------------------------------------------------------
#define ARR_BYTES   (128 * ASTR * 4)           // 6144
#define STAGE_BYTES (4 * ARR_BYTES)            // 24576
#define TOK_BYTES   512
#define GSMEM_TOTAL (2 * STAGE_BYTES + TOK_BYTES)  // 49664
#define OFF_AH 0
#define OFF_AL ARR_BYTES
#define OFF_BH (2 * ARR_BYTES)
#define OFF_BL (3 * ARR_BYTES)

__global__ void __launch_bounds__(256, 2)
gemm_mma_kernel(const float* __restrict__ bias) {
    extern __shared__ __align__(16) char smem[];
    const uint32_t sb = smem_u32(smem);
    int* s_tok = (int*)(smem + 2 * STAGE_BYTES);

    const int cnt = d_count;
    const int vBase = blockIdx.x * 128;        // compact-id base
    if (vBase >= cnt) return;

    const int tid = threadIdx.x;
    const int wid = tid >> 5;
    const int lid = tid & 31;
    const int g   = lid >> 2;
    const int t   = lid & 3;
    const int wm  = (wid & 3) * 32;
    const int wn  = (wid >> 2) * 64;
    const int cBase = blockIdx.y * 128;

    if (tid < 128) {
        int cid = vBase + tid;
        s_tok[tid] = d_used[(cid < cnt) ? cid : 0];
    }
    __syncthreads();

    const __half2* gAh = d_Ahi + (size_t)cBase * NPAIR;   // MMA B operand (n = c)
    const __half2* gAl = d_Alo + (size_t)cBase * NPAIR;

    auto load_chunk = [&](int kc, int s) {
        const uint32_t st = sb + s * STAGE_BYTES;
        const int p0 = kc * 8;                  // first pair of chunk
        // B operand rows (m = cid): gather via s_tok. 128 rows x 8 half2.
        {
            int r = tid >> 1, q = (tid & 1) * 4;
            size_t go = (size_t)s_tok[r] * NPAIR + p0 + q;
            uint32_t so = (uint32_t)(r * ASTR + q) * 4;
            cpa16(st + OFF_AH + so, d_Bhi + go);
            cpa16(st + OFF_AL + so, d_Blo + go);
        }
        // A operand rows (n = c): dense.
        {
            int r = tid >> 1, q = (tid & 1) * 4;
            size_t go = (size_t)r * NPAIR + p0 + q;
            uint32_t so = (uint32_t)(r * ASTR + q) * 4;
            cpa16(st + OFF_BH + so, gAh + go);
            cpa16(st + OFF_BL + so, gAl + go);
        }
        CPA_COMMIT();
    };

    float acc[2][8][4];
#pragma unroll
    for (int mi = 0; mi < 2; mi++)
#pragma unroll
        for (int ni = 0; ni < 8; ni++)
#pragma unroll
            for (int e = 0; e < 4; e++) acc[mi][ni][e] = 0.0f;

    load_chunk(0, 0);
    load_chunk(1, 1);

    for (int i = 0; i < NCHUNK; i++) {
        const int s = i & 1;
        if (i + 1 < NCHUNK) { CPA_WAIT1(); } else { CPA_WAIT0(); }
        __syncthreads();

        const float* sAh = (const float*)(smem + s * STAGE_BYTES + OFF_AH);
        const float* sAl = (const float*)(smem + s * STAGE_BYTES + OFF_AL);
        const float* sBh = (const float*)(smem + s * STAGE_BYTES + OFF_BH);
        const float* sBl = (const float*)(smem + s * STAGE_BYTES + OFF_BL);

        const int kcol = 2 * t;                 // pair-slot offset (floats)

        uint32_t Ah[2][4], Al[2][4];
#pragma unroll
        for (int mi = 0; mi < 2; mi++) {
            int r0 = wm + mi * 16 + g;
            float2 h0 = *(const float2*)&sAh[r0 * ASTR + kcol];
            float2 h1 = *(const float2*)&sAh[(r0 + 8) * ASTR + kcol];
            float2 l0 = *(const float2*)&sAl[r0 * ASTR + kcol];
            float2 l1 = *(const float2*)&sAl[(r0 + 8) * ASTR + kcol];
            Ah[mi][0] = __float_as_uint(h0.x); Ah[mi][1] = __float_as_uint(h1.x);
            Ah[mi][2] = __float_as_uint(h0.y); Ah[mi][3] = __float_as_uint(h1.y);
            Al[mi][0] = __float_as_uint(l0.x); Al[mi][1] = __float_as_uint(l1.x);
            Al[mi][2] = __float_as_uint(l0.y); Al[mi][3] = __float_as_uint(l1.y);
        }
#pragma unroll
        for (int ni = 0; ni < 8; ni++) {
            int rn = wn + ni * 8 + g;
            float2 h = *(const float2*)&sBh[rn * ASTR + kcol];
            float2 l = *(const float2*)&sBl[rn * ASTR + kcol];
            uint32_t bh0 = __float_as_uint(h.x), bh1 = __float_as_uint(h.y);
            uint32_t bl0 = __float_as_uint(l.x), bl1 = __float_as_uint(l.y);
#pragma unroll
            for (int mi = 0; mi < 2; mi++) {
                mma16816(acc[mi][ni], Ah[mi][0], Ah[mi][1], Ah[mi][2], Ah[mi][3], bh0, bh1);
                mma16816(acc[mi][ni], Ah[mi][0], Ah[mi][1], Ah[mi][2], Ah[mi][3], bl0, bl1);
                mma16816(acc[mi][ni], Al[mi][0], Al[mi][1], Al[mi][2], Al[mi][3], bh0, bh1);
            }
        }
        __syncthreads();
        if (i + 2 < NCHUNK) load_chunk(i + 2, s);
    }

    // ---- epilogue: +bias, logsig, float2 stores to table[cid][c] ----
#pragma unroll
    for (int ni = 0; ni < 8; ni++) {
        const int c = cBase + wn + ni * 8 + 2 * t;
        if (c >= CDIM) continue;
        const float b0 = __ldg(&bias[(c / 5) * 6 + (c % 5)]);
        const int c1 = c + 1;
        const float b1 = __ldg(&bias[(c1 / 5) * 6 + (c1 % 5)]);
#pragma unroll
        for (int mi = 0; mi < 2; mi++) {
            const int v0 = vBase + wm + mi * 16 + g;
            const int v1 = v0 + 8;
            if (v0 < cnt) {
                float2 r;
                r.x = logsig(acc[mi][ni][0] + b0);
                r.y = logsig(acc[mi][ni][1] + b1);
                *(float2*)&d_table[(size_t)v0 * TSTR + c] = r;
            }
            if (v1 < cnt) {
                float2 r;
                r.x = logsig(acc[mi][ni][2] + b0);
                r.y = logsig(acc[mi][ni][3] + b1);
                *(float2*)&d_table[(size_t)v1 * TSTR + c] = r;
            }
        }
    }
}

// ---------------------------------------------------------------------------
// 4. chunked scan: block (b, ch) covers positions [ch*32, ch*32+32) with a
//    4-token warmup; tokens remapped to compact ids.
// ---------------------------------------------------------------------------
__global__ void __launch_bounds__(160)
scan_part_kernel(const int*   __restrict__ docs,
                 const int*   __restrict__ doc_lens,
                 const float* __restrict__ wildcards) {
    const int b   = blockIdx.x;
    const int ch  = blockIdx.y;
    const int tid = threadIdx.x;
    const int p   = tid;
    const bool valid = (p < PDIM);

    const int len = doc_lens[b];
    const int c0  = ch * SCT;
    if (len <= c0) {
        if (valid) d_part[b][ch][p] = NEGF;
        return;
    }

    const int warm   = (ch == 0) ? 0 : 4;
    const int tstart = c0 - warm;
    const int nt     = warm + SCT;   // 32 or 36

    __shared__ int s_tok[SCT + 4];
    for (int i = tid; i < nt; i += 160)
        s_tok[i] = d_cid[docs[b * LDIM + tstart + i]];
    __syncthreads();

    float wl[5];
#pragma unroll
    for (int m = 0; m < 5; m++)
        wl[m] = valid ? logsig(__ldg(&wildcards[p * 5 + m])) : 0.0f;

    const int endSel = p / 50;
    float h1 = NEGF, h2 = NEGF, h3 = NEGF, h4 = NEGF, h5 = NEGF;
    float sc = NEGF;

    float pf[4][5];
#pragma unroll
    for (int u = 0; u < 4; u++) {
        if (valid && u < nt) {
            const float* row = &d_table[(size_t)s_tok[u] * TSTR + p * 5];
#pragma unroll
            for (int m = 0; m < 5; m++) pf[u][m] = __ldg(&row[m]);
        } else {
#pragma unroll
            for (int m = 0; m < 5; m++) pf[u][m] = 0.0f;
        }
    }

    const int scoreLo = warm;
    const int scoreHi = (len < c0 + SCT ? len : c0 + SCT) - tstart;

    for (int i = 0; i < nt; i += 4) {
#pragma unroll
        for (int u = 0; u < 4; u++) {
            float e0 = fmaxf(pf[u][0], wl[0]);
            float e1 = fmaxf(pf[u][1], wl[1]);
            float e2 = fmaxf(pf[u][2], wl[2]);
            float e3 = fmaxf(pf[u][3], wl[3]);
            float e4 = fmaxf(pf[u][4], wl[4]);
            h5 = h4 + e4;
            h4 = h3 + e3;
            h3 = h2 + e2;
            h2 = h1 + e1;
            h1 = e0;
            float ev = (endSel == 0) ? h3 : ((endSel == 1) ? h4 : h5);
            int li = i + u;
            sc = (li >= scoreLo && li < scoreHi) ? fmaxf(sc, ev) : sc;
            int ni = li + 4;
            if (ni < nt && valid) {
                const float* row = &d_table[(size_t)s_tok[ni] * TSTR + p * 5];
#pragma unroll
                for (int m = 0; m < 5; m++) pf[u][m] = __ldg(&row[m]);
            }
        }
    }

    if (valid) d_part[b][ch][p] = sc;
}

// ---------------------------------------------------------------------------
// 5. final: reduce chunks, exp/LN/heaviside/linear
// ---------------------------------------------------------------------------
__global__ void __launch_bounds__(160)
scan_final_kernel(const float* __restrict__ gamma,
                  const float* __restrict__ beta,
                  const float* __restrict__ W,
                  const float* __restrict__ lb,
                  float*       __restrict__ out) {
    const int b   = blockIdx.x;
    const int tid = threadIdx.x;
    const bool valid = (tid < PDIM);

    __shared__ float sh[192];
    __shared__ float sred[2];

    float sc = NEGF;
    if (valid) {
#pragma unroll
        for (int ch = 0; ch < NSC; ch++) sc = fmaxf(sc, d_part[b][ch][tid]);
    }
    float score = valid ? expf(sc) : 0.0f;

    sh[tid] = score;
    __syncthreads();
    if (tid < 32) {
        float s = 0.0f;
        for (int i = tid; i < PDIM; i += 32) s += sh[i];
#pragma unroll
        for (int o = 16; o > 0; o >>= 1) s += __shfl_down_sync(0xffffffffu, s, o);
        if (tid == 0) sred[0] = s * (1.0f / PDIM);
    }
    __syncthreads();
    const float mu = sred[0];

    float d = score - mu;
    sh[tid] = valid ? d * d : 0.0f;
    __syncthreads();
    if (tid < 32) {
        float s = 0.0f;
        for (int i = tid; i < PDIM; i += 32) s += sh[i];
#pragma unroll
        for (int o = 16; o > 0; o >>= 1) s += __shfl_down_sync(0xffffffffu, s, o);
        if (tid == 0) sred[1] = s * (1.0f / PDIM);
    }
    __syncthreads();
    const float var = sred[1];

    float bin = 0.0f;
    if (valid) {
        float norm = (score - mu) * rsqrtf(var + 1e-5f) * __ldg(&gamma[tid]) + __ldg(&beta[tid]);
        bin = (norm > 0.0f) ? 1.0f : 0.0f;
    }

    sh[tid] = valid ? bin * __ldg(&W[tid]) : 0.0f;
    __syncthreads();
    if (tid < 32) {
        float s = 0.0f;
        for (int i = tid; i < PDIM; i += 32) s += sh[i];
#pragma unroll
        for (int o = 16; o > 0; o >>= 1) s += __shfl_down_sync(0xffffffffu, s, o);
        if (tid == 0) out[b * 2 + 0] = s + __ldg(&lb[0]);
    }
    __syncthreads();
    sh[tid] = valid ? bin * __ldg(&W[PDIM + tid]) : 0.0f;
    __syncthreads();
    if (tid < 32) {
        float s = 0.0f;
        for (int i = tid; i < PDIM; i += 32) s += sh[i];
#pragma unroll
        for (int o = 16; o > 0; o >>= 1) s += __shfl_down_sync(0xffffffffu, s, o);
        if (tid == 0) out[b * 2 + 1] = s + __ldg(&lb[1]);
    }
}

// ---------------------------------------------------------------------------
// launch
// ---------------------------------------------------------------------------
extern "C" void kernel_launch(void* const* d_in, const int* in_sizes, int n_in,
                              void* d_out, int out_size) {
    const int*   docs      = (const int*)  d_in[0];
    const int*   doc_lens  = (const int*)  d_in[1];
    const float* emb       = (const float*)d_in[2];
    const float* diags     = (const float*)d_in[3];
    const float* bias      = (const float*)d_in[4];
    const float* wildcards = (const float*)d_in[5];
    const float* ln_gamma  = (const float*)d_in[6];
    const float* ln_beta   = (const float*)d_in[7];
    const float* linear_w  = (const float*)d_in[8];
    const float* linear_b  = (const float*)d_in[9];
    float*       out       = (float*)d_out;

    (void)in_sizes; (void)n_in; (void)out_size;

    cudaFuncSetAttribute(gemm_mma_kernel,
                         cudaFuncAttributeMaxDynamicSharedMemorySize, GSMEM_TOTAL);

    clear_kernel<<<(VPAD + 255) / 256, 256>>>();
    mark_kernel<<<(BDIM * LDIM + 255) / 256, 256>>>(docs, doc_lens);
    assign_kernel<<<(VDIM + 255) / 256, 256>>>();

    split_diags_kernel<<<(CPAD * NPAIR + 255) / 256, 256>>>(diags);

    dim3 tgrid((VPAD + 31) / 32, (KPAD + 31) / 32);  // (628, 10)
    split_emb_kernel<<<tgrid, dim3(32, 8)>>>(emb);

    dim3 ggrid(VPAD / 128, CPAD / 128);              // (157, 6)
    gemm_mma_kernel<<<ggrid, 256, GSMEM_TOTAL>>>(bias);

    dim3 sgrid(BDIM, NSC);                           // (64, 16)
    scan_part_kernel<<<sgrid, 160>>>(docs, doc_lens, wildcards);

    scan_final_kernel<<<BDIM, 160>>>(ln_gamma, ln_beta, linear_w, linear_b, out);
}